// round 13
// baseline (speedup 1.0000x reference)
#include <cuda_runtime.h>
#include <cuda_fp16.h>
#include <cstdint>

#define T_CAP 64
#define BATCH 256
#define DEC   1024
#define HID   1024
#define ATTN  128
#define NBLK  128
#define NTHR  512

// ---------------- persistent scratch ----------------
__device__ float  g_Uv[BATCH * T_CAP * ATTN];   // 8 MB, [b][t][a]
__device__ __half g_h_h[2][BATCH * HID];        // fp16 hidden
__device__ float  g_c[BATCH * HID];             // cell state (block-private tiles)
__device__ __half g_ctx_h[BATCH * DEC];         // fp16 context
__device__ __half g_Wih_h[4 * HID * DEC];       // fp16 W_ih (8 MB)
__device__ __half g_Whh_h[4 * HID * HID];       // fp16 W_hh (8 MB)
__device__ __half g_Wa_h[ATTN * HID];           // fp16 W_attn (256 KB)
__device__ __half g_dh_h[T_CAP * BATCH * DEC];  // fp16 feats (32 MB)
__device__ int    g_cnt;
__device__ volatile int g_flag;

// ---------------- helpers ----------------
__device__ __forceinline__ uint32_t f2tf(float f) {
    uint32_t u;
    asm("cvt.rna.tf32.f32 %0, %1;" : "=r"(u) : "f"(f));
    return u;
}

__device__ __forceinline__ void mma8(float* c, const uint32_t* a, const uint32_t* b) {
    asm volatile(
        "mma.sync.aligned.m16n8k8.row.col.f32.tf32.tf32.f32 "
        "{%0,%1,%2,%3}, {%4,%5,%6,%7}, {%8,%9}, {%0,%1,%2,%3};\n"
        : "+f"(c[0]), "+f"(c[1]), "+f"(c[2]), "+f"(c[3])
        : "r"(a[0]), "r"(a[1]), "r"(a[2]), "r"(a[3]),
          "r"(b[0]), "r"(b[1]));
}

__device__ __forceinline__ void mma16(float* c, const uint32_t* a, const uint32_t* b) {
    asm volatile(
        "mma.sync.aligned.m16n8k16.row.col.f32.f16.f16.f32 "
        "{%0,%1,%2,%3}, {%4,%5,%6,%7}, {%8,%9}, {%0,%1,%2,%3};\n"
        : "+f"(c[0]), "+f"(c[1]), "+f"(c[2]), "+f"(c[3])
        : "r"(a[0]), "r"(a[1]), "r"(a[2]), "r"(a[3]),
          "r"(b[0]), "r"(b[1]));
}

__device__ __forceinline__ void ldsm4(uint32_t* r, uint32_t addr) {
    asm volatile("ldmatrix.sync.aligned.m8n8.x4.shared.b16 {%0,%1,%2,%3}, [%4];"
                 : "=r"(r[0]), "=r"(r[1]), "=r"(r[2]), "=r"(r[3]) : "r"(addr));
}

__device__ __forceinline__ uint32_t smem_u32(const void* p) {
    return (uint32_t)__cvta_generic_to_shared(p);
}
__device__ __forceinline__ void cp16(void* s, const void* g) {
    asm volatile("cp.async.ca.shared.global [%0], [%1], 16;\n" :: "r"(smem_u32(s)), "l"(g));
}
__device__ __forceinline__ void cp16cg(void* s, const void* g) {
    asm volatile("cp.async.cg.shared.global [%0], [%1], 16;\n" :: "r"(smem_u32(s)), "l"(g));
}
#define CP_COMMIT() asm volatile("cp.async.commit_group;\n" ::)
#define CP_WAIT(n)  asm volatile("cp.async.wait_group " #n ";\n" ::)

// sub-group barriers (256 threads each)
#define BAR_ATT() asm volatile("bar.sync 1, 256;" ::: "memory")
#define BAR_GAT() asm volatile("bar.sync 2, 256;" ::: "memory")

__device__ __forceinline__ float sigf(float x) { return 1.0f / (1.0f + __expf(-x)); }
__device__ __forceinline__ float tanh_fast(float x) {
    return __fdividef(2.0f, 1.0f + __expf(-2.0f * x)) - 1.0f;
}

#define SWZ(x) ((x) ^ (((x) >> 3) & 0x70))

// grid barrier (all NBLK blocks co-resident)
__device__ __forceinline__ void gsync(int* sense) {
    __syncthreads();
    int s = *sense ^ 1;
    *sense = s;
    if (threadIdx.x == 0) {
        __threadfence();
        if (atomicAdd(&g_cnt, 1) == NBLK - 1) {
            g_cnt = 0;
            __threadfence();
            g_flag = s;
        } else {
            while (g_flag != s) __nanosleep(32);
        }
        __threadfence();
    }
    __syncthreads();
}

// ---------------- Uv tile: 128(m) x 64(n) x 1024(k), one-time (fp32 inputs) ----------------
__device__ __forceinline__ void uv_tile(
    float* smem, const float* __restrict__ dh, const float* __restrict__ U_attn,
    const float* __restrict__ b_attn, int m0, int n0)
{
    float (*As)[128][20] = (float(*)[128][20])smem;
    float (*Bs)[64][20]  = (float(*)[64][20])(smem + 5120);

    const int tid = threadIdx.x;
    const int warp = tid >> 5, lane = tid & 31;
    const int am = (tid & 255) >> 1, ak = (tid & 1) * 8;
    const int bj = (tid & 255) >> 2, bk = (tid & 3) * 4;
    const int r = m0 + am;
    const long abase = ((long)((r & 63) * 256 + (r >> 6))) * 1024;
    const long bbase = (long)(n0 + bj) * 1024;
    const bool ldr = tid < 256;

    const int wm = (warp >> 2) * 64, wn = (warp & 3) * 16;
    const int lr = lane >> 2, lc = lane & 3;

    float acc[4][2][4];
#pragma unroll
    for (int i = 0; i < 4; i++)
#pragma unroll
        for (int j = 0; j < 2; j++)
#pragma unroll
            for (int k = 0; k < 4; k++) acc[i][j][k] = 0.0f;

    const int NS = 64;
    if (ldr) {
        cp16(&As[0][am][ak],     dh + abase + ak);
        cp16(&As[0][am][ak + 4], dh + abase + ak + 4);
        cp16(&Bs[0][bj][bk],     U_attn + bbase + bk);
    }
    CP_COMMIT();

    for (int s = 0; s < NS; s++) {
        if (s + 1 < NS) {
            int buf = (s + 1) & 1, k0 = (s + 1) * 16;
            if (ldr) {
                cp16(&As[buf][am][ak],     dh + abase + k0 + ak);
                cp16(&As[buf][am][ak + 4], dh + abase + k0 + ak + 4);
                cp16(&Bs[buf][bj][bk],     U_attn + bbase + k0 + bk);
            }
            CP_COMMIT();
            CP_WAIT(1);
        } else {
            CP_WAIT(0);
        }
        __syncthreads();
        if (warp < 8) {
            const int buf = s & 1;
#pragma unroll
            for (int kk = 0; kk < 16; kk += 8) {
                uint32_t af[4][4], bf[2][2];
#pragma unroll
                for (int fm = 0; fm < 4; fm++) {
                    int rr = wm + fm * 16 + lr;
                    af[fm][0] = f2tf(As[buf][rr][kk + lc]);
                    af[fm][1] = f2tf(As[buf][rr + 8][kk + lc]);
                    af[fm][2] = f2tf(As[buf][rr][kk + lc + 4]);
                    af[fm][3] = f2tf(As[buf][rr + 8][kk + lc + 4]);
                }
#pragma unroll
                for (int fn = 0; fn < 2; fn++) {
                    int jc = wn + fn * 8 + lr;
                    bf[fn][0] = f2tf(Bs[buf][jc][kk + lc]);
                    bf[fn][1] = f2tf(Bs[buf][jc][kk + lc + 4]);
                }
#pragma unroll
                for (int fm = 0; fm < 4; fm++)
#pragma unroll
                    for (int fn = 0; fn < 2; fn++) mma8(acc[fm][fn], af[fm], bf[fn]);
            }
        }
        __syncthreads();
    }

    if (warp < 8) {
#pragma unroll
        for (int fm = 0; fm < 4; fm++) {
#pragma unroll
            for (int fn = 0; fn < 2; fn++) {
                int rr = m0 + wm + fm * 16 + lr;
                int a  = n0 + wn + fn * 8 + 2 * lc;
                float ba0 = b_attn[a], ba1 = b_attn[a + 1];
                float2 v0 = make_float2(acc[fm][fn][0] + ba0, acc[fm][fn][1] + ba1);
                float2 v1 = make_float2(acc[fm][fn][2] + ba0, acc[fm][fn][3] + ba1);
                *(float2*)&g_Uv[rr * ATTN + a]       = v0;
                *(float2*)&g_Uv[(rr + 8) * ATTN + a] = v1;
            }
        }
    }
}

// smem (bytes): A stages 8 x 16KB = 128KB ; B stages 8 x 8KB = 64KB
#define SM_A(sl)  ((sl) * 16384)
#define SM_B(sl)  (131072 + (sl) * 8192)
#define GK_SMEM_BYTES 196608

// ---------------- the persistent kernel ----------------
__global__ __launch_bounds__(NTHR, 1) void recon_kernel(
    const float* __restrict__ dh, const int* __restrict__ caps,
    const float* __restrict__ W_attn, const float* __restrict__ U_attn,
    const float* __restrict__ b_attn, const float* __restrict__ w_attn,
    const float* __restrict__ W_ih, const float* __restrict__ W_hh,
    const float* __restrict__ b_ih, const float* __restrict__ b_hh,
    float* __restrict__ out, int T_feat)
{
    extern __shared__ __align__(1024) float smem[];
    __shared__ float bias_s[64];

    const int tid = threadIdx.x, blk = blockIdx.x;
    const int warp = tid >> 5, lane = tid & 31;
    int sense = 0;

    const int gm0 = (blk & 1) * 128;
    const int gn0 = (blk >> 1) * 16;

    char* smem_c = (char*)smem;
    const uint32_t smem_base = smem_u32(smem);

    if (tid < 64) {
        int row = (tid & 3) * 1024 + gn0 + (tid >> 2);
        bias_s[tid] = b_ih[row] + b_hh[row];
    }

    // ---- phase 0: init + fp16 conversions + Uv ----
    for (int i = blk * NTHR + tid; i < BATCH * HID; i += NBLK * NTHR) {
        g_h_h[0][i] = __float2half_rn(0.0f);
        g_c[i]      = 0.0f;
    }
    for (int i = blk * NTHR + tid; i < 4 * HID * DEC; i += NBLK * NTHR)
        g_Wih_h[i] = __float2half_rn(W_ih[i]);
    for (int i = blk * NTHR + tid; i < 4 * HID * HID; i += NBLK * NTHR)
        g_Whh_h[i] = __float2half_rn(W_hh[i]);
    for (int i = blk * NTHR + tid; i < ATTN * HID; i += NBLK * NTHR)
        g_Wa_h[i] = __float2half_rn(W_attn[i]);
    for (int i = blk * NTHR + tid; i < (T_CAP * BATCH * DEC) / 8; i += NBLK * NTHR) {
        float4 x = ((const float4*)dh)[2 * i];
        float4 y = ((const float4*)dh)[2 * i + 1];
        __half2 p0 = __floats2half2_rn(x.x, x.y);
        __half2 p1 = __floats2half2_rn(x.z, x.w);
        __half2 p2 = __floats2half2_rn(y.x, y.y);
        __half2 p3 = __floats2half2_rn(y.z, y.w);
        uint4 pk;
        pk.x = *(uint32_t*)&p0; pk.y = *(uint32_t*)&p1;
        pk.z = *(uint32_t*)&p2; pk.w = *(uint32_t*)&p3;
        ((uint4*)g_dh_h)[i] = pk;
    }
    for (int tix = blk; tix < 256; tix += NBLK)
        uv_tile(smem, dh, U_attn, b_attn, (tix & 127) * 128, (tix >> 7) * 64);
    gsync(&sense);

    // ---- ctx-half loaders (all 512 threads) ----
    const int a_row = tid >> 2;
    const int a_c   = (tid & 3) * 16;
    const long a_goff = (long)(gm0 + a_row) * 1024 + a_c;
    const int a_so  = a_row * 128 + a_c * 2;
    const int b_row = tid >> 3;
    const int b_c   = (tid & 7) * 8;
    const long b_goff = (long)((b_row & 3) * 1024 + gn0 + (b_row >> 2)) * 1024 + b_c;
    const int b_so  = b_row * 128 + b_c * 2;

    // ---- h-half loaders (256 threads, warps 8-15; t2 = tid-256) ----
    const int t2 = tid & 255;
    const int ha_row = t2 >> 1;
    const int ha_c   = (t2 & 1) * 32;                  // halves
    const long ha_goff = (long)(gm0 + ha_row) * 1024 + ha_c;
    const int ha_so  = ha_row * 128 + ha_c * 2;        // bytes
    const int hb_row = t2 >> 2;
    const int hb_c   = (t2 & 3) * 16;
    const long hb_goff = (long)((hb_row & 3) * 1024 + gn0 + (hb_row >> 2)) * 1024 + hb_c;
    const int hb_so  = hb_row * 128 + hb_c * 2;

    // ---- MMA mapping: 2 groups x 8 warps; warp tile 32m x 32j (4m x 2j) ----
    const int grp = warp >> 3;
    const int wg  = warp & 7;
    const int wm  = (wg & 3) * 32;
    const int wn  = (wg >> 2) * 32;
    const int ls_row = ((lane >> 3) & 1) * 8 + (lane & 7);
    const int ls_colb = (lane >> 4) * 16;
    const uint32_t a_swz = SWZ((uint32_t)((wm + ls_row) * 128 + ls_colb));
    const uint32_t b_swz = SWZ((uint32_t)((wn + ls_row) * 128 + ls_colb));
    const int lr = lane >> 2, lc = lane & 3;

    for (int s = 0; s < T_feat; s++) {
        const __half* hprev_h = g_h_h[s & 1];
        __half* hnext_h = g_h_h[(s + 1) & 1];

        float acc[2][4][4];

        if (warp < 8) {
            // ============ phase A (warps 0-7): attention for rows (2blk, 2blk+1) ============
            const int b0 = blk * 2;
            __half* hs_h = (__half*)smem;      // [2][1024] halves = 4 KB
            float* whs = smem + 1024;          // [2][128]
            float* wa  = smem + 1280;          // [128]
            float* es  = smem + 1536;          // [2][64]
            float* ps  = smem + 1664;          // [2][64]

            cp16cg(hs_h + tid * 8, (const __half*)hprev_h + b0 * HID + tid * 8);
            CP_COMMIT();
            if (tid < ATTN) wa[tid] = w_attn[tid];
            CP_WAIT(0);
            BAR_ATT();

            // Wh: warp owns 16 a-cols
            const uint4* hs4 = (const uint4*)hs_h;
#pragma unroll
            for (int rr = 0; rr < 16; rr++) {
                int a = warp * 16 + rr;
                const uint4* wrow = (const uint4*)(g_Wa_h + a * 1024);
                float d0 = 0.f, d1 = 0.f;
#pragma unroll
                for (int j = 0; j < 4; j++) {
                    uint4 w4 = wrow[j * 32 + lane];
                    uint4 x4 = hs4[j * 32 + lane];
                    uint4 y4 = hs4[128 + j * 32 + lane];
                    const __half2* wh2 = (const __half2*)&w4;
                    const __half2* xh2 = (const __half2*)&x4;
                    const __half2* yh2 = (const __half2*)&y4;
#pragma unroll
                    for (int q = 0; q < 4; q++) {
                        float2 wf = __half22float2(wh2[q]);
                        float2 xf = __half22float2(xh2[q]);
                        float2 yf = __half22float2(yh2[q]);
                        d0 += wf.x * xf.x + wf.y * xf.y;
                        d1 += wf.x * yf.x + wf.y * yf.y;
                    }
                }
#pragma unroll
                for (int off = 16; off; off >>= 1) {
                    d0 += __shfl_xor_sync(0xffffffffu, d0, off);
                    d1 += __shfl_xor_sync(0xffffffffu, d1, off);
                }
                if (lane == 0) { whs[a] = d0; whs[128 + a] = d1; }
            }
            BAR_ATT();

            for (int t = warp; t < T_CAP; t += 8) {
#pragma unroll
                for (int bi = 0; bi < 2; bi++) {
                    const float* uv = g_Uv + ((long)(b0 + bi) * T_CAP + t) * ATTN;
                    float sE = 0.f;
#pragma unroll
                    for (int q = 0; q < 4; q++) {
                        int a = lane + q * 32;
                        sE += wa[a] * tanh_fast(whs[bi * 128 + a] + uv[a]);
                    }
#pragma unroll
                    for (int off = 16; off; off >>= 1)
                        sE += __shfl_xor_sync(0xffffffffu, sE, off);
                    if (lane == 0) {
                        int cp = caps[t * BATCH + b0 + bi];
                        es[bi * 64 + t] = (cp != 0 && cp != 2) ? sE : -1e30f;
                    }
                }
            }
            BAR_ATT();

            if (warp < 2) {
                int bi = warp;
                float e0 = es[bi * 64 + lane], e1 = es[bi * 64 + lane + 32];
                float mx = fmaxf(e0, e1);
#pragma unroll
                for (int off = 16; off; off >>= 1)
                    mx = fmaxf(mx, __shfl_xor_sync(0xffffffffu, mx, off));
                float x0 = __expf(e0 - mx), x1 = __expf(e1 - mx);
                float sm = x0 + x1;
#pragma unroll
                for (int off = 16; off; off >>= 1)
                    sm += __shfl_xor_sync(0xffffffffu, sm, off);
                float inv = 1.0f / sm;
                ps[bi * 64 + lane]      = x0 * inv;
                ps[bi * 64 + lane + 32] = x1 * inv;
            }
            BAR_ATT();

            // ctx: 256 threads x 8 consecutive d
            {
                const int row = tid >> 7;
                const int d8 = (tid & 127) * 8;
                float c0 = 0.f, c1 = 0.f, c2 = 0.f, c3 = 0.f;
                float c4 = 0.f, c5 = 0.f, c6 = 0.f, c7 = 0.f;
                const float* pr = ps + row * 64;
#pragma unroll 4
                for (int t = 0; t < T_CAP; t++) {
                    float p = pr[t];
                    uint4 v = *(const uint4*)&g_dh_h[(long)(t * BATCH + b0 + row) * DEC + d8];
                    float2 f0 = __half22float2(*(__half2*)&v.x);
                    float2 f1 = __half22float2(*(__half2*)&v.y);
                    float2 f2 = __half22float2(*(__half2*)&v.z);
                    float2 f3 = __half22float2(*(__half2*)&v.w);
                    c0 += p * f0.x; c1 += p * f0.y; c2 += p * f1.x; c3 += p * f1.y;
                    c4 += p * f2.x; c5 += p * f2.y; c6 += p * f3.x; c7 += p * f3.y;
                }
                __half2 o0 = __floats2half2_rn(c0, c1);
                __half2 o1 = __floats2half2_rn(c2, c3);
                __half2 o2 = __floats2half2_rn(c4, c5);
                __half2 o3 = __floats2half2_rn(c6, c7);
                uint4 pk;
                pk.x = *(uint32_t*)&o0; pk.y = *(uint32_t*)&o1;
                pk.z = *(uint32_t*)&o2; pk.w = *(uint32_t*)&o3;
                *(uint4*)&g_ctx_h[(long)(b0 + row) * DEC + d8] = pk;
            }
        } else {
            // ============ phase A (warps 8-15): gates h-half, k = 1024..2047 ============
#pragma unroll
            for (int i = 0; i < 2; i++)
#pragma unroll
                for (int j = 0; j < 4; j++)
#pragma unroll
                    for (int k = 0; k < 4; k++) acc[i][j][k] = 0.0f;

            auto load_hstage = [&](int p) {   // stage p of 16; slot 4 + (p&3)
                int kb = p * 64;
                const __half* Asrc = hprev_h + ha_goff + kb;
                const __half* Bsrc = g_Whh_h + hb_goff + kb;
                char* Ab = smem_c + SM_A(4 + (p & 3));
                char* Bb = smem_c + SM_B(4 + (p & 3));
#pragma unroll
                for (int j = 0; j < 4; j++)
                    cp16cg(Ab + SWZ(ha_so + j * 16), Asrc + j * 8);
#pragma unroll
                for (int j = 0; j < 2; j++)
                    cp16(Bb + SWZ(hb_so + j * 16), Bsrc + j * 8);
                CP_COMMIT();
            };

            load_hstage(0);
            load_hstage(1);

            for (int p = 0; p < 16; p++) {
                if (p + 2 < 16) {
                    load_hstage(p + 2);
                    CP_WAIT(2);
                } else if (p + 1 < 16) {
                    CP_WAIT(1);
                } else {
                    CP_WAIT(0);
                }
                BAR_GAT();

                const uint32_t Ab = smem_base + SM_A(4 + (p & 3));
                const uint32_t Bb = smem_base + SM_B(4 + (p & 3));
#pragma unroll
                for (int kk = 0; kk < 4; kk++) {
                    const uint32_t kofs = (uint32_t)(kk * 32);
                    uint32_t af0[4], af1[4], bfa[4], bfb[4];
                    ldsm4(af0, Ab + (a_swz ^ kofs));
                    ldsm4(af1, Ab + 2048 + (a_swz ^ kofs));
                    ldsm4(bfa, Bb + (b_swz ^ kofs));
                    ldsm4(bfb, Bb + 2048 + (b_swz ^ kofs));
                    uint32_t b0[2] = {bfa[0], bfa[2]};
                    uint32_t b1[2] = {bfa[1], bfa[3]};
                    uint32_t b2[2] = {bfb[0], bfb[2]};
                    uint32_t b3[2] = {bfb[1], bfb[3]};
                    mma16(acc[0][0], af0, b0);
                    mma16(acc[0][1], af0, b1);
                    mma16(acc[0][2], af0, b2);
                    mma16(acc[0][3], af0, b3);
                    mma16(acc[1][0], af1, b0);
                    mma16(acc[1][1], af1, b1);
                    mma16(acc[1][2], af1, b2);
                    mma16(acc[1][3], af1, b3);
                }
            }
        }

        gsync(&sense);   // join warp groups + global ctx visibility

        // ============ phase C (all warps): gates ctx-half, k = 0..1023 ============
        {
            if (warp < 8) {
#pragma unroll
                for (int i = 0; i < 2; i++)
#pragma unroll
                    for (int j = 0; j < 4; j++)
#pragma unroll
                        for (int k = 0; k < 4; k++) acc[i][j][k] = 0.0f;
            }

            auto load_cstage = [&](int p) {   // stage p of 16; slot p&7
                int kb = p * 64;
                const __half* Asrc = g_ctx_h + a_goff + kb;
                const __half* Bsrc = g_Wih_h + b_goff + kb;
                char* Ab = smem_c + SM_A(p & 7);
                char* Bb = smem_c + SM_B(p & 7);
                cp16cg(Ab + SWZ(a_so),      Asrc);
                cp16cg(Ab + SWZ(a_so + 16), Asrc + 8);
                cp16(Bb + SWZ(b_so), Bsrc);
                CP_COMMIT();
            };

#pragma unroll
            for (int p = 0; p < 4; p++) load_cstage(p);

            for (int u = 0; u < 8; u++) {
                int f = 2 * u + 4;
                if (f < 16)     load_cstage(f);
                if (f + 1 < 16) load_cstage(f + 1);
                if (u <= 5)      { CP_WAIT(4); }
                else if (u == 6) { CP_WAIT(2); }
                else             { CP_WAIT(0); }
                __syncthreads();

                const int sl = (2 * u + grp) & 7;
                const uint32_t Ab = smem_base + SM_A(sl);
                const uint32_t Bb = smem_base + SM_B(sl);
#pragma unroll
                for (int kk = 0; kk < 4; kk++) {
                    const uint32_t kofs = (uint32_t)(kk * 32);
                    uint32_t af0[4], af1[4], bfa[4], bfb[4];
                    ldsm4(af0, Ab + (a_swz ^ kofs));
                    ldsm4(af1, Ab + 2048 + (a_swz ^ kofs));
                    ldsm4(bfa, Bb + (b_swz ^ kofs));
                    ldsm4(bfb, Bb + 2048 + (b_swz ^ kofs));
                    uint32_t b0[2] = {bfa[0], bfa[2]};
                    uint32_t b1[2] = {bfa[1], bfa[3]};
                    uint32_t b2[2] = {bfb[0], bfb[2]};
                    uint32_t b3[2] = {bfb[1], bfb[3]};
                    mma16(acc[0][0], af0, b0);
                    mma16(acc[0][1], af0, b1);
                    mma16(acc[0][2], af0, b2);
                    mma16(acc[0][3], af0, b3);
                    mma16(acc[1][0], af1, b0);
                    mma16(acc[1][1], af1, b1);
                    mma16(acc[1][2], af1, b2);
                    mma16(acc[1][3], af1, b3);
                }
            }

            __syncthreads();  // stage smem dead; overlay two gates tiles

            float (*gs0)[68] = (float(*)[68])smem;            // grp 0 (ctx-even)
            float (*gs1)[68] = (float(*)[68])(smem + 8704);   // grp 1 (h-half + ctx-odd)
            {
                float (*gs)[68] = (grp == 0) ? gs0 : gs1;
#pragma unroll
                for (int fm = 0; fm < 2; fm++) {
#pragma unroll
                    for (int fn = 0; fn < 4; fn++) {
                        int m = wm + fm * 16 + lr;
                        int j = wn + fn * 8 + 2 * lc;
                        *(float2*)&gs[m][j]     = make_float2(acc[fm][fn][0], acc[fm][fn][1]);
                        *(float2*)&gs[m + 8][j] = make_float2(acc[fm][fn][2], acc[fm][fn][3]);
                    }
                }
            }
            __syncthreads();

            for (int q = tid; q < 128 * 16; q += NTHR) {
                int ml = q & 127, nl = q >> 7;
                float4 ga = *(float4*)&gs0[ml][nl * 4];
                float4 gb = *(float4*)&gs1[ml][nl * 4];
                float iv = ga.x + gb.x + bias_s[nl * 4 + 0];
                float fv = ga.y + gb.y + bias_s[nl * 4 + 1];
                float gv = ga.z + gb.z + bias_s[nl * 4 + 2];
                float ov = ga.w + gb.w + bias_s[nl * 4 + 3];
                int b = gm0 + ml, n = gn0 + nl;
                int idx = b * HID + n;
                float cold = g_c[idx];
                float cn = sigf(fv) * cold + sigf(iv) * tanhf(gv);
                float hn = sigf(ov) * tanhf(cn);
                g_c[idx] = cn;
                hnext_h[idx] = __float2half_rn(hn);
                out[(long)(b * T_feat + s) * HID + n] = hn;
            }
        }
        gsync(&sense);
    }

    gsync(&sense);  // total barriers even -> g_flag restored to 0
}

// ---------------- launcher ----------------
extern "C" void kernel_launch(void* const* d_in, const int* in_sizes, int n_in,
                              void* d_out, int out_size)
{
    int base = 2;
    if (n_in >= 11 && in_sizes[2] == 1) base = 3;

    const float* dh     = (const float*)d_in[0];
    const int*   caps   = (const int*)d_in[1];
    const float* W_attn = (const float*)d_in[base + 0];
    const float* U_attn = (const float*)d_in[base + 1];
    const float* b_attn = (const float*)d_in[base + 2];
    const float* w_attn = (const float*)d_in[base + 3];
    const float* W_ih   = (const float*)d_in[base + 4];
    const float* W_hh   = (const float*)d_in[base + 5];
    const float* b_ih   = (const float*)d_in[base + 6];
    const float* b_hh   = (const float*)d_in[base + 7];
    float* out = (float*)d_out;

    const int T_feat = out_size / (BATCH * HID);  // 28

    static int configured = 0;
    if (!configured) {
        cudaFuncSetAttribute(recon_kernel, cudaFuncAttributeMaxDynamicSharedMemorySize,
                             GK_SMEM_BYTES);
        configured = 1;
    }

    recon_kernel<<<NBLK, NTHR, GK_SMEM_BYTES>>>(
        dh, caps, W_attn, U_attn, b_attn, w_attn,
        W_ih, W_hh, b_ih, b_hh, out, T_feat);
}

// round 14
// speedup vs baseline: 1.0295x; 1.0295x over previous
#include <cuda_runtime.h>
#include <cuda_fp16.h>
#include <cstdint>

#define T_CAP 64
#define BATCH 256
#define DEC   1024
#define HID   1024
#define ATTN  128
#define NBLK  128
#define NTHR  512

// ---------------- persistent scratch ----------------
__device__ float  g_Uv[BATCH * T_CAP * ATTN];   // 8 MB, [b][t][a]
__device__ __half g_h_h[2][BATCH * HID];        // fp16 hidden (gates + attention)
__device__ float  g_c[BATCH * HID];             // cell state (block-private tiles)
__device__ __half g_ctx_h[BATCH * DEC];         // fp16 context
__device__ __half g_Wih_h[4 * HID * DEC];       // fp16 W_ih (8 MB)
__device__ __half g_Whh_h[4 * HID * HID];       // fp16 W_hh (8 MB)
__device__ __half g_Wa_h[ATTN * HID];           // fp16 W_attn (256 KB)
__device__ __half g_dh_h[T_CAP * BATCH * DEC];  // fp16 feats (32 MB)
__device__ volatile int g_arr[NBLK];            // distributed arrivals (returns to 0)
__device__ volatile int g_rel;                  // release flag (returns to 0)

// ---------------- helpers ----------------
__device__ __forceinline__ uint32_t f2tf(float f) {
    uint32_t u;
    asm("cvt.rna.tf32.f32 %0, %1;" : "=r"(u) : "f"(f));
    return u;
}

__device__ __forceinline__ void mma8(float* c, const uint32_t* a, const uint32_t* b) {
    asm volatile(
        "mma.sync.aligned.m16n8k8.row.col.f32.tf32.tf32.f32 "
        "{%0,%1,%2,%3}, {%4,%5,%6,%7}, {%8,%9}, {%0,%1,%2,%3};\n"
        : "+f"(c[0]), "+f"(c[1]), "+f"(c[2]), "+f"(c[3])
        : "r"(a[0]), "r"(a[1]), "r"(a[2]), "r"(a[3]),
          "r"(b[0]), "r"(b[1]));
}

__device__ __forceinline__ void mma16(float* c, const uint32_t* a, const uint32_t* b) {
    asm volatile(
        "mma.sync.aligned.m16n8k16.row.col.f32.f16.f16.f32 "
        "{%0,%1,%2,%3}, {%4,%5,%6,%7}, {%8,%9}, {%0,%1,%2,%3};\n"
        : "+f"(c[0]), "+f"(c[1]), "+f"(c[2]), "+f"(c[3])
        : "r"(a[0]), "r"(a[1]), "r"(a[2]), "r"(a[3]),
          "r"(b[0]), "r"(b[1]));
}

__device__ __forceinline__ void ldsm4(uint32_t* r, uint32_t addr) {
    asm volatile("ldmatrix.sync.aligned.m8n8.x4.shared.b16 {%0,%1,%2,%3}, [%4];"
                 : "=r"(r[0]), "=r"(r[1]), "=r"(r[2]), "=r"(r[3]) : "r"(addr));
}

__device__ __forceinline__ uint32_t smem_u32(const void* p) {
    return (uint32_t)__cvta_generic_to_shared(p);
}
__device__ __forceinline__ void cp16(void* s, const void* g) {
    asm volatile("cp.async.ca.shared.global [%0], [%1], 16;\n" :: "r"(smem_u32(s)), "l"(g));
}
__device__ __forceinline__ void cp16cg(void* s, const void* g) {
    asm volatile("cp.async.cg.shared.global [%0], [%1], 16;\n" :: "r"(smem_u32(s)), "l"(g));
}
#define CP_COMMIT() asm volatile("cp.async.commit_group;\n" ::)
#define CP_WAIT(n)  asm volatile("cp.async.wait_group " #n ";\n" ::)

__device__ __forceinline__ float sigf(float x) { return 1.0f / (1.0f + __expf(-x)); }
__device__ __forceinline__ float tanh_fast(float x) {
    return __fdividef(2.0f, 1.0f + __expf(-2.0f * x)) - 1.0f;
}

#define SWZ(x) ((x) ^ (((x) >> 3) & 0x70))

// distributed grid barrier: parallel arrivals, block 0 aggregates.
// 58 barriers per launch (even) -> g_arr/g_rel return to 0 for graph replay.
__device__ __forceinline__ void gsync(int* sense) {
    __syncthreads();
    int s = *sense ^ 1;
    *sense = s;
    if (blockIdx.x == 0) {
        if (threadIdx.x == 0) {
            __threadfence();
            g_arr[0] = s;
        }
        if (threadIdx.x < NBLK) {
            while (g_arr[threadIdx.x] != s) __nanosleep(32);
        }
        __syncthreads();
        if (threadIdx.x == 0) {
            __threadfence();
            g_rel = s;
        }
    } else {
        if (threadIdx.x == 0) {
            __threadfence();
            g_arr[blockIdx.x] = s;
            while (g_rel != s) __nanosleep(32);
            __threadfence();
        }
        __syncthreads();
    }
}

// ---------------- Uv tile: 128(m) x 64(n) x 1024(k), one-time (fp32 inputs) ----------------
__device__ __forceinline__ void uv_tile(
    float* smem, const float* __restrict__ dh, const float* __restrict__ U_attn,
    const float* __restrict__ b_attn, int m0, int n0)
{
    float (*As)[128][20] = (float(*)[128][20])smem;
    float (*Bs)[64][20]  = (float(*)[64][20])(smem + 5120);

    const int tid = threadIdx.x;
    const int warp = tid >> 5, lane = tid & 31;
    const int am = (tid & 255) >> 1, ak = (tid & 1) * 8;
    const int bj = (tid & 255) >> 2, bk = (tid & 3) * 4;
    const int r = m0 + am;
    const long abase = ((long)((r & 63) * 256 + (r >> 6))) * 1024;
    const long bbase = (long)(n0 + bj) * 1024;
    const bool ldr = tid < 256;

    const int wm = (warp >> 2) * 64, wn = (warp & 3) * 16;
    const int lr = lane >> 2, lc = lane & 3;

    float acc[4][2][4];
#pragma unroll
    for (int i = 0; i < 4; i++)
#pragma unroll
        for (int j = 0; j < 2; j++)
#pragma unroll
            for (int k = 0; k < 4; k++) acc[i][j][k] = 0.0f;

    const int NS = 64;
    if (ldr) {
        cp16(&As[0][am][ak],     dh + abase + ak);
        cp16(&As[0][am][ak + 4], dh + abase + ak + 4);
        cp16(&Bs[0][bj][bk],     U_attn + bbase + bk);
    }
    CP_COMMIT();

    for (int s = 0; s < NS; s++) {
        if (s + 1 < NS) {
            int buf = (s + 1) & 1, k0 = (s + 1) * 16;
            if (ldr) {
                cp16(&As[buf][am][ak],     dh + abase + k0 + ak);
                cp16(&As[buf][am][ak + 4], dh + abase + k0 + ak + 4);
                cp16(&Bs[buf][bj][bk],     U_attn + bbase + k0 + bk);
            }
            CP_COMMIT();
            CP_WAIT(1);
        } else {
            CP_WAIT(0);
        }
        __syncthreads();
        if (warp < 8) {
            const int buf = s & 1;
#pragma unroll
            for (int kk = 0; kk < 16; kk += 8) {
                uint32_t af[4][4], bf[2][2];
#pragma unroll
                for (int fm = 0; fm < 4; fm++) {
                    int rr = wm + fm * 16 + lr;
                    af[fm][0] = f2tf(As[buf][rr][kk + lc]);
                    af[fm][1] = f2tf(As[buf][rr + 8][kk + lc]);
                    af[fm][2] = f2tf(As[buf][rr][kk + lc + 4]);
                    af[fm][3] = f2tf(As[buf][rr + 8][kk + lc + 4]);
                }
#pragma unroll
                for (int fn = 0; fn < 2; fn++) {
                    int jc = wn + fn * 8 + lr;
                    bf[fn][0] = f2tf(Bs[buf][jc][kk + lc]);
                    bf[fn][1] = f2tf(Bs[buf][jc][kk + lc + 4]);
                }
#pragma unroll
                for (int fm = 0; fm < 4; fm++)
#pragma unroll
                    for (int fn = 0; fn < 2; fn++) mma8(acc[fm][fn], af[fm], bf[fn]);
            }
        }
        __syncthreads();
    }

    if (warp < 8) {
#pragma unroll
        for (int fm = 0; fm < 4; fm++) {
#pragma unroll
            for (int fn = 0; fn < 2; fn++) {
                int rr = m0 + wm + fm * 16 + lr;
                int a  = n0 + wn + fn * 8 + 2 * lc;
                float ba0 = b_attn[a], ba1 = b_attn[a + 1];
                float2 v0 = make_float2(acc[fm][fn][0] + ba0, acc[fm][fn][1] + ba1);
                float2 v1 = make_float2(acc[fm][fn][2] + ba0, acc[fm][fn][3] + ba1);
                *(float2*)&g_Uv[rr * ATTN + a]       = v0;
                *(float2*)&g_Uv[(rr + 8) * ATTN + a] = v1;
            }
        }
    }
}

// smem (bytes): A stages 8 x 16KB = 128KB ; B stages 8 x 8KB = 64KB
#define SM_A(sl)  ((sl) * 16384)
#define SM_B(sl)  (131072 + (sl) * 8192)
#define GK_SMEM_BYTES 196608

// ---------------- the persistent kernel ----------------
__global__ __launch_bounds__(NTHR, 1) void recon_kernel(
    const float* __restrict__ dh, const int* __restrict__ caps,
    const float* __restrict__ W_attn, const float* __restrict__ U_attn,
    const float* __restrict__ b_attn, const float* __restrict__ w_attn,
    const float* __restrict__ W_ih, const float* __restrict__ W_hh,
    const float* __restrict__ b_ih, const float* __restrict__ b_hh,
    float* __restrict__ out, int T_feat)
{
    extern __shared__ __align__(1024) float smem[];
    __shared__ float bias_s[64];

    const int tid = threadIdx.x, blk = blockIdx.x;
    const int warp = tid >> 5, lane = tid & 31;
    int sense = 0;

    const int gm0 = (blk & 1) * 128;
    const int gn0 = (blk >> 1) * 16;

    char* smem_c = (char*)smem;
    const uint32_t smem_base = smem_u32(smem);

    if (tid < 64) {
        int row = (tid & 3) * 1024 + gn0 + (tid >> 2);
        bias_s[tid] = b_ih[row] + b_hh[row];
    }

    // ---- phase 0: init + fp16 conversions + Uv ----
    for (int i = blk * NTHR + tid; i < BATCH * HID; i += NBLK * NTHR) {
        g_h_h[0][i] = __float2half_rn(0.0f);
        g_c[i]      = 0.0f;
    }
    for (int i = blk * NTHR + tid; i < 4 * HID * DEC; i += NBLK * NTHR)
        g_Wih_h[i] = __float2half_rn(W_ih[i]);
    for (int i = blk * NTHR + tid; i < 4 * HID * HID; i += NBLK * NTHR)
        g_Whh_h[i] = __float2half_rn(W_hh[i]);
    for (int i = blk * NTHR + tid; i < ATTN * HID; i += NBLK * NTHR)
        g_Wa_h[i] = __float2half_rn(W_attn[i]);
    for (int i = blk * NTHR + tid; i < (T_CAP * BATCH * DEC) / 8; i += NBLK * NTHR) {
        float4 x = ((const float4*)dh)[2 * i];
        float4 y = ((const float4*)dh)[2 * i + 1];
        __half2 p0 = __floats2half2_rn(x.x, x.y);
        __half2 p1 = __floats2half2_rn(x.z, x.w);
        __half2 p2 = __floats2half2_rn(y.x, y.y);
        __half2 p3 = __floats2half2_rn(y.z, y.w);
        uint4 pk;
        pk.x = *(uint32_t*)&p0; pk.y = *(uint32_t*)&p1;
        pk.z = *(uint32_t*)&p2; pk.w = *(uint32_t*)&p3;
        ((uint4*)g_dh_h)[i] = pk;
    }
    for (int tix = blk; tix < 256; tix += NBLK)
        uv_tile(smem, dh, U_attn, b_attn, (tix & 127) * 128, (tix >> 7) * 64);
    gsync(&sense);

    // ---- gates loaders: A 128 rows x 64k fp16 (16KB), B 64 j x 64k fp16 (8KB) ----
    const int a_row = tid >> 2;
    const int a_c   = (tid & 3) * 16;
    const long a_goff = (long)(gm0 + a_row) * 1024 + a_c;
    const int a_so  = a_row * 128 + a_c * 2;
    const int b_row = tid >> 3;
    const int b_c   = (tid & 7) * 8;
    const long b_goff = (long)((b_row & 3) * 1024 + gn0 + (b_row >> 2)) * 1024 + b_c;
    const int b_so  = b_row * 128 + b_c * 2;

    // ---- k-split: 2 groups x 8 warps; warp tile 32m x 32j (4m x 2j grid) ----
    const int grp = warp >> 3;
    const int wg  = warp & 7;
    const int wm  = (wg & 3) * 32;
    const int wn  = (wg >> 2) * 32;
    const int ls_row = ((lane >> 3) & 1) * 8 + (lane & 7);
    const int ls_colb = (lane >> 4) * 16;
    const uint32_t a_swz = SWZ((uint32_t)((wm + ls_row) * 128 + ls_colb));
    const uint32_t b_swz = SWZ((uint32_t)((wn + ls_row) * 128 + ls_colb));
    const int lr = lane >> 2, lc = lane & 3;

    for (int s = 0; s < T_feat; s++) {
        const __half* hprev_h = g_h_h[s & 1];
        __half* hnext_h = g_h_h[(s + 1) & 1];

        // gates stage loader: processing order p=0..31 -> stage (p+16)&31 (h-half first),
        // slot (p+4)&7 (preload slots 4-7 avoid attention smem at 0-16KB).
        auto load_stage = [&](int p) {
            int st = (p + 16) & 31;
            int sl = (p + 4) & 7;
            int k0 = st * 64;
            int kb = k0 & 1023;
            const __half* Asrc = ((k0 < 1024) ? g_ctx_h : hprev_h) + a_goff + kb;
            const __half* Bsrc = ((k0 < 1024) ? g_Wih_h : g_Whh_h) + b_goff + kb;
            char* Ab = smem_c + SM_A(sl);
            char* Bb = smem_c + SM_B(sl);
            cp16cg(Ab + SWZ(a_so),      Asrc);
            cp16cg(Ab + SWZ(a_so + 16), Asrc + 8);
            cp16(Bb + SWZ(b_so), Bsrc);
            CP_COMMIT();
        };

        // ================= attention: 2 batch rows per block (fp16 inputs) =================
        {
            const int b0 = blk * 2;
            __half* hs_h = (__half*)smem;      // [2][1024] halves = 4 KB
            float* whs = smem + 1024;          // [2][128]
            float* wa  = smem + 1280;          // [128]
            float* es  = smem + 1536;          // [2][64]
            float* ps  = smem + 1664;          // [2][64]

            if (tid < 256)
                cp16cg(hs_h + tid * 8, (const __half*)hprev_h + b0 * HID + tid * 8);
            CP_COMMIT();
            if (tid < ATTN) wa[tid] = w_attn[tid];
            CP_WAIT(0);
            __syncthreads();

            // Wh: warp w owns 8 a-cols; fp16 W and h, fp32 accumulate
            const uint4* hs4 = (const uint4*)hs_h;
#pragma unroll
            for (int rr = 0; rr < 8; rr++) {
                int a = warp * 8 + rr;
                const uint4* wrow = (const uint4*)(g_Wa_h + a * 1024);
                float d0 = 0.f, d1 = 0.f;
#pragma unroll
                for (int j = 0; j < 4; j++) {
                    uint4 w4 = wrow[j * 32 + lane];
                    uint4 x4 = hs4[j * 32 + lane];
                    uint4 y4 = hs4[128 + j * 32 + lane];
                    const __half2* wh2 = (const __half2*)&w4;
                    const __half2* xh2 = (const __half2*)&x4;
                    const __half2* yh2 = (const __half2*)&y4;
#pragma unroll
                    for (int q = 0; q < 4; q++) {
                        float2 wf = __half22float2(wh2[q]);
                        float2 xf = __half22float2(xh2[q]);
                        float2 yf = __half22float2(yh2[q]);
                        d0 += wf.x * xf.x + wf.y * xf.y;
                        d1 += wf.x * yf.x + wf.y * yf.y;
                    }
                }
#pragma unroll
                for (int off = 16; off; off >>= 1) {
                    d0 += __shfl_xor_sync(0xffffffffu, d0, off);
                    d1 += __shfl_xor_sync(0xffffffffu, d1, off);
                }
                if (lane == 0) { whs[a] = d0; whs[128 + a] = d1; }
            }
            __syncthreads();

            for (int t = warp; t < T_CAP; t += 16) {
#pragma unroll
                for (int bi = 0; bi < 2; bi++) {
                    const float* uv = g_Uv + ((long)(b0 + bi) * T_CAP + t) * ATTN;
                    float sE = 0.f;
#pragma unroll
                    for (int q = 0; q < 4; q++) {
                        int a = lane + q * 32;
                        sE += wa[a] * tanh_fast(whs[bi * 128 + a] + uv[a]);
                    }
#pragma unroll
                    for (int off = 16; off; off >>= 1)
                        sE += __shfl_xor_sync(0xffffffffu, sE, off);
                    if (lane == 0) {
                        int cp = caps[t * BATCH + b0 + bi];
                        es[bi * 64 + t] = (cp != 0 && cp != 2) ? sE : -1e30f;
                    }
                }
            }
            __syncthreads();

            if (warp < 2) {
                int bi = warp;
                float e0 = es[bi * 64 + lane], e1 = es[bi * 64 + lane + 32];
                float mx = fmaxf(e0, e1);
#pragma unroll
                for (int off = 16; off; off >>= 1)
                    mx = fmaxf(mx, __shfl_xor_sync(0xffffffffu, mx, off));
                float x0 = __expf(e0 - mx), x1 = __expf(e1 - mx);
                float sm = x0 + x1;
#pragma unroll
                for (int off = 16; off; off >>= 1)
                    sm += __shfl_xor_sync(0xffffffffu, sm, off);
                float inv = 1.0f / sm;
                ps[bi * 64 + lane]      = x0 * inv;
                ps[bi * 64 + lane + 32] = x1 * inv;
            }
            __syncthreads();

            // ctx from fp16 feats, fp32 accumulate
            {
                const int row = tid >> 8;
                const int d4 = (tid & 255) * 4;
                float a0 = 0.f, a1 = 0.f, a2 = 0.f, a3 = 0.f;
                const float* pr = ps + row * 64;
#pragma unroll 4
                for (int t = 0; t < T_CAP; t++) {
                    float p = pr[t];
                    uint2 v = *(const uint2*)&g_dh_h[(long)(t * BATCH + b0 + row) * DEC + d4];
                    float2 f0 = __half22float2(*(__half2*)&v.x);
                    float2 f1 = __half22float2(*(__half2*)&v.y);
                    a0 += p * f0.x; a1 += p * f0.y; a2 += p * f1.x; a3 += p * f1.y;
                }
                __half2 o0 = __floats2half2_rn(a0, a1);
                __half2 o1 = __floats2half2_rn(a2, a3);
                uint2 pk;
                pk.x = *(uint32_t*)&o0;
                pk.y = *(uint32_t*)&o1;
                *(uint2*)&g_ctx_h[(long)(b0 + row) * DEC + d4] = pk;
            }
        }

        // preload first 4 gates stages (h-half: depends only on hprev + W_hh) — these
        // cp.asyncs fly during the grid barrier; slots 4-7 don't touch attention smem.
        load_stage(0);
        load_stage(1);
        load_stage(2);
        load_stage(3);

        gsync(&sense);

        // ===== gates: 128m x 64j x 2048k fp16; pair k-split, h-half first =====
        {
            const int NP = 16;   // stage pairs

            float acc[2][4][4];
#pragma unroll
            for (int i = 0; i < 2; i++)
#pragma unroll
                for (int j = 0; j < 4; j++)
#pragma unroll
                    for (int k = 0; k < 4; k++) acc[i][j][k] = 0.0f;

            for (int t = 0; t < NP; t++) {
                int f = 2 * t + 4;
                if (f < 32)     load_stage(f);
                if (f + 1 < 32) load_stage(f + 1);
                if (t <= NP - 3)      { CP_WAIT(4); }
                else if (t == NP - 2) { CP_WAIT(2); }
                else                  { CP_WAIT(0); }
                __syncthreads();

                const int sl = (2 * t + grp + 4) & 7;
                const uint32_t Ab = smem_base + SM_A(sl);
                const uint32_t Bb = smem_base + SM_B(sl);
#pragma unroll
                for (int kk = 0; kk < 4; kk++) {
                    const uint32_t kofs = (uint32_t)(kk * 32);
                    uint32_t af0[4], af1[4], bfa[4], bfb[4];
                    ldsm4(af0, Ab + (a_swz ^ kofs));
                    ldsm4(af1, Ab + 2048 + (a_swz ^ kofs));
                    ldsm4(bfa, Bb + (b_swz ^ kofs));
                    ldsm4(bfb, Bb + 2048 + (b_swz ^ kofs));
                    uint32_t b0[2] = {bfa[0], bfa[2]};
                    uint32_t b1[2] = {bfa[1], bfa[3]};
                    uint32_t b2[2] = {bfb[0], bfb[2]};
                    uint32_t b3[2] = {bfb[1], bfb[3]};
                    mma16(acc[0][0], af0, b0);
                    mma16(acc[0][1], af0, b1);
                    mma16(acc[0][2], af0, b2);
                    mma16(acc[0][3], af0, b3);
                    mma16(acc[1][0], af1, b0);
                    mma16(acc[1][1], af1, b1);
                    mma16(acc[1][2], af1, b2);
                    mma16(acc[1][3], af1, b3);
                }
            }

            __syncthreads();  // stage smem dead; overlay two gates tiles

            float (*gs0)[68] = (float(*)[68])smem;            // grp 0
            float (*gs1)[68] = (float(*)[68])(smem + 8704);   // grp 1
            {
                float (*gs)[68] = (grp == 0) ? gs0 : gs1;
#pragma unroll
                for (int fm = 0; fm < 2; fm++) {
#pragma unroll
                    for (int fn = 0; fn < 4; fn++) {
                        int m = wm + fm * 16 + lr;
                        int j = wn + fn * 8 + 2 * lc;
                        *(float2*)&gs[m][j]     = make_float2(acc[fm][fn][0], acc[fm][fn][1]);
                        *(float2*)&gs[m + 8][j] = make_float2(acc[fm][fn][2], acc[fm][fn][3]);
                    }
                }
            }
            __syncthreads();

            for (int q = tid; q < 128 * 16; q += NTHR) {
                int ml = q & 127, nl = q >> 7;
                float4 ga = *(float4*)&gs0[ml][nl * 4];
                float4 gb = *(float4*)&gs1[ml][nl * 4];
                float iv = ga.x + gb.x + bias_s[nl * 4 + 0];
                float fv = ga.y + gb.y + bias_s[nl * 4 + 1];
                float gv = ga.z + gb.z + bias_s[nl * 4 + 2];
                float ov = ga.w + gb.w + bias_s[nl * 4 + 3];
                int b = gm0 + ml, n = gn0 + nl;
                int idx = b * HID + n;
                float cold = g_c[idx];
                float cn = sigf(fv) * cold + sigf(iv) * tanhf(gv);
                float hn = sigf(ov) * tanhf(cn);
                g_c[idx] = cn;
                hnext_h[idx] = __float2half_rn(hn);
                out[(long)(b * T_feat + s) * HID + n] = hn;
            }
        }
        gsync(&sense);
    }

    gsync(&sense);  // total barriers even (58) -> g_arr/g_rel restored to 0
}

// ---------------- launcher ----------------
extern "C" void kernel_launch(void* const* d_in, const int* in_sizes, int n_in,
                              void* d_out, int out_size)
{
    int base = 2;
    if (n_in >= 11 && in_sizes[2] == 1) base = 3;

    const float* dh     = (const float*)d_in[0];
    const int*   caps   = (const int*)d_in[1];
    const float* W_attn = (const float*)d_in[base + 0];
    const float* U_attn = (const float*)d_in[base + 1];
    const float* b_attn = (const float*)d_in[base + 2];
    const float* w_attn = (const float*)d_in[base + 3];
    const float* W_ih   = (const float*)d_in[base + 4];
    const float* W_hh   = (const float*)d_in[base + 5];
    const float* b_ih   = (const float*)d_in[base + 6];
    const float* b_hh   = (const float*)d_in[base + 7];
    float* out = (float*)d_out;

    const int T_feat = out_size / (BATCH * HID);  // 28

    static int configured = 0;
    if (!configured) {
        cudaFuncSetAttribute(recon_kernel, cudaFuncAttributeMaxDynamicSharedMemorySize,
                             GK_SMEM_BYTES);
        configured = 1;
    }

    recon_kernel<<<NBLK, NTHR, GK_SMEM_BYTES>>>(
        dh, caps, W_attn, U_attn, b_attn, w_attn,
        W_ih, W_hh, b_ih, b_hh, out, T_feat);
}

// round 16
// speedup vs baseline: 1.0709x; 1.0401x over previous
#include <cuda_runtime.h>
#include <cuda_fp16.h>
#include <cstdint>

#define T_CAP 64
#define BATCH 256
#define DEC   1024
#define HID   1024
#define ATTN  128
#define NBLK  128
#define NTHR  512

// ---------------- persistent scratch ----------------
__device__ __half g_Uv_h[BATCH * T_CAP * ATTN]; // 4 MB fp16, [b][t][a]
__device__ __half g_h_h[2][BATCH * HID];        // fp16 hidden (gates + attention)
__device__ float  g_c[BATCH * HID];             // cell state (block-private tiles)
__device__ __half g_ctx_h[BATCH * DEC];         // fp16 context
__device__ __half g_Wih_h[4 * HID * DEC];       // fp16 W_ih (8 MB)
__device__ __half g_Whh_h[4 * HID * HID];       // fp16 W_hh (8 MB)
__device__ __half g_Wa_h[ATTN * HID];           // fp16 W_attn (256 KB)
__device__ __half g_dh_h[T_CAP * BATCH * DEC];  // fp16 feats (32 MB)
__device__ int    g_cnt;
__device__ volatile int g_flag;

// ---------------- helpers ----------------
__device__ __forceinline__ uint32_t f2tf(float f) {
    uint32_t u;
    asm("cvt.rna.tf32.f32 %0, %1;" : "=r"(u) : "f"(f));
    return u;
}

__device__ __forceinline__ void mma8(float* c, const uint32_t* a, const uint32_t* b) {
    asm volatile(
        "mma.sync.aligned.m16n8k8.row.col.f32.tf32.tf32.f32 "
        "{%0,%1,%2,%3}, {%4,%5,%6,%7}, {%8,%9}, {%0,%1,%2,%3};\n"
        : "+f"(c[0]), "+f"(c[1]), "+f"(c[2]), "+f"(c[3])
        : "r"(a[0]), "r"(a[1]), "r"(a[2]), "r"(a[3]),
          "r"(b[0]), "r"(b[1]));
}

__device__ __forceinline__ void mma16(float* c, const uint32_t* a, const uint32_t* b) {
    asm volatile(
        "mma.sync.aligned.m16n8k16.row.col.f32.f16.f16.f32 "
        "{%0,%1,%2,%3}, {%4,%5,%6,%7}, {%8,%9}, {%0,%1,%2,%3};\n"
        : "+f"(c[0]), "+f"(c[1]), "+f"(c[2]), "+f"(c[3])
        : "r"(a[0]), "r"(a[1]), "r"(a[2]), "r"(a[3]),
          "r"(b[0]), "r"(b[1]));
}

__device__ __forceinline__ void ldsm4(uint32_t* r, uint32_t addr) {
    asm volatile("ldmatrix.sync.aligned.m8n8.x4.shared.b16 {%0,%1,%2,%3}, [%4];"
                 : "=r"(r[0]), "=r"(r[1]), "=r"(r[2]), "=r"(r[3]) : "r"(addr));
}

__device__ __forceinline__ uint32_t smem_u32(const void* p) {
    return (uint32_t)__cvta_generic_to_shared(p);
}
__device__ __forceinline__ void cp16(void* s, const void* g) {
    asm volatile("cp.async.ca.shared.global [%0], [%1], 16;\n" :: "r"(smem_u32(s)), "l"(g));
}
__device__ __forceinline__ void cp16cg(void* s, const void* g) {
    asm volatile("cp.async.cg.shared.global [%0], [%1], 16;\n" :: "r"(smem_u32(s)), "l"(g));
}
#define CP_COMMIT() asm volatile("cp.async.commit_group;\n" ::)
#define CP_WAIT(n)  asm volatile("cp.async.wait_group " #n ";\n" ::)

__device__ __forceinline__ float sigf(float x) { return 1.0f / (1.0f + __expf(-x)); }
__device__ __forceinline__ float tanh_fast(float x) {
    return __fdividef(2.0f, 1.0f + __expf(-2.0f * x)) - 1.0f;
}

#define SWZ(x) ((x) ^ (((x) >> 3) & 0x70))

// grid barrier (all NBLK blocks co-resident)
__device__ __forceinline__ void gsync(int* sense) {
    __syncthreads();
    int s = *sense ^ 1;
    *sense = s;
    if (threadIdx.x == 0) {
        __threadfence();
        if (atomicAdd(&g_cnt, 1) == NBLK - 1) {
            g_cnt = 0;
            __threadfence();
            g_flag = s;
        } else {
            while (g_flag != s) __nanosleep(32);
        }
        __threadfence();
    }
    __syncthreads();
}

// ---------------- Uv tile: 128(m) x 64(n) x 1024(k), one-time (fp32 in, fp16 out) ----------------
__device__ __forceinline__ void uv_tile(
    float* smem, const float* __restrict__ dh, const float* __restrict__ U_attn,
    const float* __restrict__ b_attn, int m0, int n0)
{
    float (*As)[128][20] = (float(*)[128][20])smem;
    float (*Bs)[64][20]  = (float(*)[64][20])(smem + 5120);

    const int tid = threadIdx.x;
    const int warp = tid >> 5, lane = tid & 31;
    const int am = (tid & 255) >> 1, ak = (tid & 1) * 8;
    const int bj = (tid & 255) >> 2, bk = (tid & 3) * 4;
    const int r = m0 + am;
    const long abase = ((long)((r & 63) * 256 + (r >> 6))) * 1024;
    const long bbase = (long)(n0 + bj) * 1024;
    const bool ldr = tid < 256;

    const int wm = (warp >> 2) * 64, wn = (warp & 3) * 16;
    const int lr = lane >> 2, lc = lane & 3;

    float acc[4][2][4];
#pragma unroll
    for (int i = 0; i < 4; i++)
#pragma unroll
        for (int j = 0; j < 2; j++)
#pragma unroll
            for (int k = 0; k < 4; k++) acc[i][j][k] = 0.0f;

    const int NS = 64;
    if (ldr) {
        cp16(&As[0][am][ak],     dh + abase + ak);
        cp16(&As[0][am][ak + 4], dh + abase + ak + 4);
        cp16(&Bs[0][bj][bk],     U_attn + bbase + bk);
    }
    CP_COMMIT();

    for (int s = 0; s < NS; s++) {
        if (s + 1 < NS) {
            int buf = (s + 1) & 1, k0 = (s + 1) * 16;
            if (ldr) {
                cp16(&As[buf][am][ak],     dh + abase + k0 + ak);
                cp16(&As[buf][am][ak + 4], dh + abase + k0 + ak + 4);
                cp16(&Bs[buf][bj][bk],     U_attn + bbase + k0 + bk);
            }
            CP_COMMIT();
            CP_WAIT(1);
        } else {
            CP_WAIT(0);
        }
        __syncthreads();
        if (warp < 8) {
            const int buf = s & 1;
#pragma unroll
            for (int kk = 0; kk < 16; kk += 8) {
                uint32_t af[4][4], bf[2][2];
#pragma unroll
                for (int fm = 0; fm < 4; fm++) {
                    int rr = wm + fm * 16 + lr;
                    af[fm][0] = f2tf(As[buf][rr][kk + lc]);
                    af[fm][1] = f2tf(As[buf][rr + 8][kk + lc]);
                    af[fm][2] = f2tf(As[buf][rr][kk + lc + 4]);
                    af[fm][3] = f2tf(As[buf][rr + 8][kk + lc + 4]);
                }
#pragma unroll
                for (int fn = 0; fn < 2; fn++) {
                    int jc = wn + fn * 8 + lr;
                    bf[fn][0] = f2tf(Bs[buf][jc][kk + lc]);
                    bf[fn][1] = f2tf(Bs[buf][jc][kk + lc + 4]);
                }
#pragma unroll
                for (int fm = 0; fm < 4; fm++)
#pragma unroll
                    for (int fn = 0; fn < 2; fn++) mma8(acc[fm][fn], af[fm], bf[fn]);
            }
        }
        __syncthreads();
    }

    if (warp < 8) {
#pragma unroll
        for (int fm = 0; fm < 4; fm++) {
#pragma unroll
            for (int fn = 0; fn < 2; fn++) {
                int rr = m0 + wm + fm * 16 + lr;
                int a  = n0 + wn + fn * 8 + 2 * lc;
                float ba0 = b_attn[a], ba1 = b_attn[a + 1];
                __half2 v0 = __floats2half2_rn(acc[fm][fn][0] + ba0, acc[fm][fn][1] + ba1);
                __half2 v1 = __floats2half2_rn(acc[fm][fn][2] + ba0, acc[fm][fn][3] + ba1);
                *(uint32_t*)&g_Uv_h[rr * ATTN + a]       = *(uint32_t*)&v0;
                *(uint32_t*)&g_Uv_h[(rr + 8) * ATTN + a] = *(uint32_t*)&v1;
            }
        }
    }
}

// smem (bytes): A stages 8 x 16KB = 128KB ; B stages 8 x 8KB = 64KB
#define SM_A(sl)  ((sl) * 16384)
#define SM_B(sl)  (131072 + (sl) * 8192)
#define GK_SMEM_BYTES 196608

// ---------------- the persistent kernel ----------------
__global__ __launch_bounds__(NTHR, 1) void recon_kernel(
    const float* __restrict__ dh, const int* __restrict__ caps,
    const float* __restrict__ W_attn, const float* __restrict__ U_attn,
    const float* __restrict__ b_attn, const float* __restrict__ w_attn,
    const float* __restrict__ W_ih, const float* __restrict__ W_hh,
    const float* __restrict__ b_ih, const float* __restrict__ b_hh,
    float* __restrict__ out, int T_feat)
{
    extern __shared__ __align__(1024) float smem[];
    __shared__ float bias_s[64];

    const int tid = threadIdx.x, blk = blockIdx.x;
    const int warp = tid >> 5, lane = tid & 31;
    int sense = 0;

    const int gm0 = (blk & 1) * 128;
    const int gn0 = (blk >> 1) * 16;

    char* smem_c = (char*)smem;
    const uint32_t smem_base = smem_u32(smem);

    if (tid < 64) {
        int row = (tid & 3) * 1024 + gn0 + (tid >> 2);
        bias_s[tid] = b_ih[row] + b_hh[row];
    }

    // ---- phase 0: init + fp16 conversions + Uv ----
    for (int i = blk * NTHR + tid; i < BATCH * HID; i += NBLK * NTHR) {
        g_h_h[0][i] = __float2half_rn(0.0f);
        g_c[i]      = 0.0f;
    }
    for (int i = blk * NTHR + tid; i < 4 * HID * DEC; i += NBLK * NTHR)
        g_Wih_h[i] = __float2half_rn(W_ih[i]);
    for (int i = blk * NTHR + tid; i < 4 * HID * HID; i += NBLK * NTHR)
        g_Whh_h[i] = __float2half_rn(W_hh[i]);
    for (int i = blk * NTHR + tid; i < ATTN * HID; i += NBLK * NTHR)
        g_Wa_h[i] = __float2half_rn(W_attn[i]);
    for (int i = blk * NTHR + tid; i < (T_CAP * BATCH * DEC) / 8; i += NBLK * NTHR) {
        float4 x = ((const float4*)dh)[2 * i];
        float4 y = ((const float4*)dh)[2 * i + 1];
        __half2 p0 = __floats2half2_rn(x.x, x.y);
        __half2 p1 = __floats2half2_rn(x.z, x.w);
        __half2 p2 = __floats2half2_rn(y.x, y.y);
        __half2 p3 = __floats2half2_rn(y.z, y.w);
        uint4 pk;
        pk.x = *(uint32_t*)&p0; pk.y = *(uint32_t*)&p1;
        pk.z = *(uint32_t*)&p2; pk.w = *(uint32_t*)&p3;
        ((uint4*)g_dh_h)[i] = pk;
    }
    for (int tix = blk; tix < 256; tix += NBLK)
        uv_tile(smem, dh, U_attn, b_attn, (tix & 127) * 128, (tix >> 7) * 64);

    // caption masks for this block's two batch rows (constant across steps)
    uint64_t mk[2];
    {
        const int b0 = blk * 2;
#pragma unroll
        for (int bi = 0; bi < 2; bi++) {
            uint64_t m = 0;
            for (int t = 0; t < T_CAP; t++) {
                int cp = __ldg(&caps[t * BATCH + b0 + bi]);
                if (cp != 0 && cp != 2) m |= (1ull << t);
            }
            mk[bi] = m;
        }
    }
    gsync(&sense);

    // ---- gates loaders: A 128 rows x 64k fp16 (16KB), B 64 j x 64k fp16 (8KB) ----
    const int a_row = tid >> 2;
    const int a_c   = (tid & 3) * 16;
    const long a_goff = (long)(gm0 + a_row) * 1024 + a_c;
    const int a_so  = a_row * 128 + a_c * 2;
    const int b_row = tid >> 3;
    const int b_c   = (tid & 7) * 8;
    const long b_goff = (long)((b_row & 3) * 1024 + gn0 + (b_row >> 2)) * 1024 + b_c;
    const int b_so  = b_row * 128 + b_c * 2;

    // ---- k-split: 2 groups x 8 warps; warp tile 32m x 32j (4m x 2j grid) ----
    const int grp = warp >> 3;
    const int wg  = warp & 7;
    const int wm  = (wg & 3) * 32;
    const int wn  = (wg >> 2) * 32;
    const int ls_row = ((lane >> 3) & 1) * 8 + (lane & 7);
    const int ls_colb = (lane >> 4) * 16;
    const uint32_t a_swz = SWZ((uint32_t)((wm + ls_row) * 128 + ls_colb));
    const uint32_t b_swz = SWZ((uint32_t)((wn + ls_row) * 128 + ls_colb));
    const int lr = lane >> 2, lc = lane & 3;

    for (int s = 0; s < T_feat; s++) {
        const __half* hprev_h = g_h_h[s & 1];
        __half* hnext_h = g_h_h[(s + 1) & 1];

        // gates stage loader: processing order p=0..31 -> stage (p+16)&31 (h-half first),
        // slot (p+4)&7 (preload slots 4-7 avoid attention smem at 0-16KB).
        auto load_stage = [&](int p) {
            int st = (p + 16) & 31;
            int sl = (p + 4) & 7;
            int k0 = st * 64;
            int kb = k0 & 1023;
            const __half* Asrc = ((k0 < 1024) ? g_ctx_h : hprev_h) + a_goff + kb;
            const __half* Bsrc = ((k0 < 1024) ? g_Wih_h : g_Whh_h) + b_goff + kb;
            char* Ab = smem_c + SM_A(sl);
            char* Bb = smem_c + SM_B(sl);
            cp16cg(Ab + SWZ(a_so),      Asrc);
            cp16cg(Ab + SWZ(a_so + 16), Asrc + 8);
            cp16(Bb + SWZ(b_so), Bsrc);
            CP_COMMIT();
        };

        // ================= attention: 2 batch rows per block (fp16 inputs) =================
        {
            const int b0 = blk * 2;
            __half* hs_h = (__half*)smem;      // [2][1024] halves = 4 KB
            float* whs = smem + 1024;          // [2][128]
            float* wa  = smem + 1280;          // [128]
            float* es  = smem + 1536;          // [2][64]
            float* ps  = smem + 1664;          // [2][64]

            if (tid < 256)
                cp16cg(hs_h + tid * 8, (const __half*)hprev_h + b0 * HID + tid * 8);
            CP_COMMIT();
            if (tid < ATTN) wa[tid] = w_attn[tid];
            CP_WAIT(0);
            __syncthreads();

            // Wh: warp w owns 8 a-cols; fp16 W and h, fp32 accumulate
            const uint4* hs4 = (const uint4*)hs_h;
#pragma unroll
            for (int rr = 0; rr < 8; rr++) {
                int a = warp * 8 + rr;
                const uint4* wrow = (const uint4*)(g_Wa_h + a * 1024);
                float d0 = 0.f, d1 = 0.f;
#pragma unroll
                for (int j = 0; j < 4; j++) {
                    uint4 w4 = wrow[j * 32 + lane];
                    uint4 x4 = hs4[j * 32 + lane];
                    uint4 y4 = hs4[128 + j * 32 + lane];
                    const __half2* wh2 = (const __half2*)&w4;
                    const __half2* xh2 = (const __half2*)&x4;
                    const __half2* yh2 = (const __half2*)&y4;
#pragma unroll
                    for (int q = 0; q < 4; q++) {
                        float2 wf = __half22float2(wh2[q]);
                        float2 xf = __half22float2(xh2[q]);
                        float2 yf = __half22float2(yh2[q]);
                        d0 += wf.x * xf.x + wf.y * xf.y;
                        d1 += wf.x * yf.x + wf.y * yf.y;
                    }
                }
#pragma unroll
                for (int off = 16; off; off >>= 1) {
                    d0 += __shfl_xor_sync(0xffffffffu, d0, off);
                    d1 += __shfl_xor_sync(0xffffffffu, d1, off);
                }
                if (lane == 0) { whs[a] = d0; whs[128 + a] = d1; }
            }
            __syncthreads();

            // energies: fp16 Uv, mask from registers
            for (int t = warp; t < T_CAP; t += 16) {
#pragma unroll
                for (int bi = 0; bi < 2; bi++) {
                    const __half* uv = g_Uv_h + ((long)(b0 + bi) * T_CAP + t) * ATTN;
                    uint2 v = *(const uint2*)(uv + lane * 4);
                    float4 wv = *(float4*)&wa[lane * 4];
                    float4 hv = *(float4*)&whs[bi * 128 + lane * 4];
                    float2 f0 = __half22float2(*(__half2*)&v.x);
                    float2 f1 = __half22float2(*(__half2*)&v.y);
                    float sE = wv.x * tanh_fast(hv.x + f0.x)
                             + wv.y * tanh_fast(hv.y + f0.y)
                             + wv.z * tanh_fast(hv.z + f1.x)
                             + wv.w * tanh_fast(hv.w + f1.y);
#pragma unroll
                    for (int off = 16; off; off >>= 1)
                        sE += __shfl_xor_sync(0xffffffffu, sE, off);
                    if (lane == 0)
                        es[bi * 64 + t] = ((mk[bi] >> t) & 1) ? sE : -1e30f;
                }
            }
            __syncthreads();

            if (warp < 2) {
                int bi = warp;
                float e0 = es[bi * 64 + lane], e1 = es[bi * 64 + lane + 32];
                float mx = fmaxf(e0, e1);
#pragma unroll
                for (int off = 16; off; off >>= 1)
                    mx = fmaxf(mx, __shfl_xor_sync(0xffffffffu, mx, off));
                float x0 = __expf(e0 - mx), x1 = __expf(e1 - mx);
                float sm = x0 + x1;
#pragma unroll
                for (int off = 16; off; off >>= 1)
                    sm += __shfl_xor_sync(0xffffffffu, sm, off);
                float inv = 1.0f / sm;
                ps[bi * 64 + lane]      = x0 * inv;
                ps[bi * 64 + lane + 32] = x1 * inv;
            }
            __syncthreads();

            // ctx from fp16 feats, fp32 accumulate
            {
                const int row = tid >> 8;
                const int d4 = (tid & 255) * 4;
                float a0 = 0.f, a1 = 0.f, a2 = 0.f, a3 = 0.f;
                const float* pr = ps + row * 64;
#pragma unroll 4
                for (int t = 0; t < T_CAP; t++) {
                    float p = pr[t];
                    uint2 v = *(const uint2*)&g_dh_h[(long)(t * BATCH + b0 + row) * DEC + d4];
                    float2 f0 = __half22float2(*(__half2*)&v.x);
                    float2 f1 = __half22float2(*(__half2*)&v.y);
                    a0 += p * f0.x; a1 += p * f0.y; a2 += p * f1.x; a3 += p * f1.y;
                }
                __half2 o0 = __floats2half2_rn(a0, a1);
                __half2 o1 = __floats2half2_rn(a2, a3);
                uint2 pk;
                pk.x = *(uint32_t*)&o0;
                pk.y = *(uint32_t*)&o1;
                *(uint2*)&g_ctx_h[(long)(b0 + row) * DEC + d4] = pk;
            }
        }

        // preload first 4 gates stages (h-half: depends only on hprev + W_hh)
        load_stage(0);
        load_stage(1);
        load_stage(2);
        load_stage(3);

        gsync(&sense);

        // ===== gates: 128m x 64j x 2048k fp16; pair k-split, h-half first =====
        {
            const int NP = 16;   // stage pairs

            float acc[2][4][4];
#pragma unroll
            for (int i = 0; i < 2; i++)
#pragma unroll
                for (int j = 0; j < 4; j++)
#pragma unroll
                    for (int k = 0; k < 4; k++) acc[i][j][k] = 0.0f;

            for (int t = 0; t < NP; t++) {
                int f = 2 * t + 4;
                if (f < 32)     load_stage(f);
                if (f + 1 < 32) load_stage(f + 1);
                if (t <= NP - 3)      { CP_WAIT(4); }
                else if (t == NP - 2) { CP_WAIT(2); }
                else                  { CP_WAIT(0); }
                __syncthreads();

                const int sl = (2 * t + grp + 4) & 7;
                const uint32_t Ab = smem_base + SM_A(sl);
                const uint32_t Bb = smem_base + SM_B(sl);
#pragma unroll
                for (int kk = 0; kk < 4; kk++) {
                    const uint32_t kofs = (uint32_t)(kk * 32);
                    uint32_t af0[4], af1[4], bfa[4], bfb[4];
                    ldsm4(af0, Ab + (a_swz ^ kofs));
                    ldsm4(af1, Ab + 2048 + (a_swz ^ kofs));
                    ldsm4(bfa, Bb + (b_swz ^ kofs));
                    ldsm4(bfb, Bb + 2048 + (b_swz ^ kofs));
                    uint32_t b0[2] = {bfa[0], bfa[2]};
                    uint32_t b1[2] = {bfa[1], bfa[3]};
                    uint32_t b2[2] = {bfb[0], bfb[2]};
                    uint32_t b3[2] = {bfb[1], bfb[3]};
                    mma16(acc[0][0], af0, b0);
                    mma16(acc[0][1], af0, b1);
                    mma16(acc[0][2], af0, b2);
                    mma16(acc[0][3], af0, b3);
                    mma16(acc[1][0], af1, b0);
                    mma16(acc[1][1], af1, b1);
                    mma16(acc[1][2], af1, b2);
                    mma16(acc[1][3], af1, b3);
                }
            }

            __syncthreads();  // stage smem dead; overlay two gates tiles

            float (*gs0)[68] = (float(*)[68])smem;            // grp 0
            float (*gs1)[68] = (float(*)[68])(smem + 8704);   // grp 1
            {
                float (*gs)[68] = (grp == 0) ? gs0 : gs1;
#pragma unroll
                for (int fm = 0; fm < 2; fm++) {
#pragma unroll
                    for (int fn = 0; fn < 4; fn++) {
                        int m = wm + fm * 16 + lr;
                        int j = wn + fn * 8 + 2 * lc;
                        *(float2*)&gs[m][j]     = make_float2(acc[fm][fn][0], acc[fm][fn][1]);
                        *(float2*)&gs[m + 8][j] = make_float2(acc[fm][fn][2], acc[fm][fn][3]);
                    }
                }
            }
            __syncthreads();

            for (int q = tid; q < 128 * 16; q += NTHR) {
                int ml = q & 127, nl = q >> 7;
                float4 ga = *(float4*)&gs0[ml][nl * 4];
                float4 gb = *(float4*)&gs1[ml][nl * 4];
                float iv = ga.x + gb.x + bias_s[nl * 4 + 0];
                float fv = ga.y + gb.y + bias_s[nl * 4 + 1];
                float gv = ga.z + gb.z + bias_s[nl * 4 + 2];
                float ov = ga.w + gb.w + bias_s[nl * 4 + 3];
                int b = gm0 + ml, n = gn0 + nl;
                int idx = b * HID + n;
                float cold = g_c[idx];
                float cn = sigf(fv) * cold + sigf(iv) * tanhf(gv);
                float hn = sigf(ov) * tanhf(cn);
                g_c[idx] = cn;
                hnext_h[idx] = __float2half_rn(hn);
                out[(long)(b * T_feat + s) * HID + n] = hn;
            }
        }
        gsync(&sense);
    }

    gsync(&sense);  // total barriers even -> g_flag restored to 0
}

// ---------------- launcher ----------------
extern "C" void kernel_launch(void* const* d_in, const int* in_sizes, int n_in,
                              void* d_out, int out_size)
{
    int base = 2;
    if (n_in >= 11 && in_sizes[2] == 1) base = 3;

    const float* dh     = (const float*)d_in[0];
    const int*   caps   = (const int*)d_in[1];
    const float* W_attn = (const float*)d_in[base + 0];
    const float* U_attn = (const float*)d_in[base + 1];
    const float* b_attn = (const float*)d_in[base + 2];
    const float* w_attn = (const float*)d_in[base + 3];
    const float* W_ih   = (const float*)d_in[base + 4];
    const float* W_hh   = (const float*)d_in[base + 5];
    const float* b_ih   = (const float*)d_in[base + 6];
    const float* b_hh   = (const float*)d_in[base + 7];
    float* out = (float*)d_out;

    const int T_feat = out_size / (BATCH * HID);  // 28

    static int configured = 0;
    if (!configured) {
        cudaFuncSetAttribute(recon_kernel, cudaFuncAttributeMaxDynamicSharedMemorySize,
                             GK_SMEM_BYTES);
        configured = 1;
    }

    recon_kernel<<<NBLK, NTHR, GK_SMEM_BYTES>>>(
        dh, caps, W_attn, U_attn, b_attn, w_attn,
        W_ih, W_hh, b_ih, b_hh, out, T_feat);
}

// round 17
// speedup vs baseline: 1.1316x; 1.0567x over previous
#include <cuda_runtime.h>
#include <cuda_fp16.h>
#include <cstdint>

#define T_CAP 64
#define BATCH 256
#define DEC   1024
#define HID   1024
#define ATTN  128
#define NBLK  128
#define NTHR  512

// ---------------- persistent scratch ----------------
__device__ __half g_Uv_h[BATCH * T_CAP * ATTN]; // 4 MB fp16, [b][t][a]
__device__ __half g_h_h[2][BATCH * HID];        // fp16 hidden (gates + attention)
__device__ float  g_c[BATCH * HID];             // cell state (block-private tiles)
__device__ __half g_ctx_h[BATCH * DEC];         // fp16 context
__device__ __half g_Wih_h[4 * HID * DEC];       // fp16 W_ih (8 MB)
__device__ __half g_Whh_h[4 * HID * HID];       // fp16 W_hh (8 MB)
__device__ __half g_Wa_h[ATTN * HID];           // fp16 W_attn (256 KB)
__device__ __half g_Ua_h[ATTN * DEC];           // fp16 U_attn (256 KB)
__device__ __half g_dh_h[T_CAP * BATCH * DEC];  // fp16 feats (32 MB)
__device__ int    g_cnt;
__device__ volatile int g_flag;

// ---------------- helpers ----------------
__device__ __forceinline__ void mma16(float* c, const uint32_t* a, const uint32_t* b) {
    asm volatile(
        "mma.sync.aligned.m16n8k16.row.col.f32.f16.f16.f32 "
        "{%0,%1,%2,%3}, {%4,%5,%6,%7}, {%8,%9}, {%0,%1,%2,%3};\n"
        : "+f"(c[0]), "+f"(c[1]), "+f"(c[2]), "+f"(c[3])
        : "r"(a[0]), "r"(a[1]), "r"(a[2]), "r"(a[3]),
          "r"(b[0]), "r"(b[1]));
}

__device__ __forceinline__ void ldsm4(uint32_t* r, uint32_t addr) {
    asm volatile("ldmatrix.sync.aligned.m8n8.x4.shared.b16 {%0,%1,%2,%3}, [%4];"
                 : "=r"(r[0]), "=r"(r[1]), "=r"(r[2]), "=r"(r[3]) : "r"(addr));
}

__device__ __forceinline__ uint32_t smem_u32(const void* p) {
    return (uint32_t)__cvta_generic_to_shared(p);
}
__device__ __forceinline__ void cp16(void* s, const void* g) {
    asm volatile("cp.async.ca.shared.global [%0], [%1], 16;\n" :: "r"(smem_u32(s)), "l"(g));
}
__device__ __forceinline__ void cp16cg(void* s, const void* g) {
    asm volatile("cp.async.cg.shared.global [%0], [%1], 16;\n" :: "r"(smem_u32(s)), "l"(g));
}
#define CP_COMMIT() asm volatile("cp.async.commit_group;\n" ::)
#define CP_WAIT(n)  asm volatile("cp.async.wait_group " #n ";\n" ::)

__device__ __forceinline__ float sigf(float x) { return 1.0f / (1.0f + __expf(-x)); }
__device__ __forceinline__ float tanh_fast(float x) {
    return __fdividef(2.0f, 1.0f + __expf(-2.0f * x)) - 1.0f;
}

#define SWZ(x) ((x) ^ (((x) >> 3) & 0x70))

// grid barrier (all NBLK blocks co-resident)
__device__ __forceinline__ void gsync(int* sense) {
    __syncthreads();
    int s = *sense ^ 1;
    *sense = s;
    if (threadIdx.x == 0) {
        __threadfence();
        if (atomicAdd(&g_cnt, 1) == NBLK - 1) {
            g_cnt = 0;
            __threadfence();
            g_flag = s;
        } else {
            while (g_flag != s) __nanosleep(32);
        }
        __threadfence();
    }
    __syncthreads();
}

// smem (bytes): A stages 8 x 16KB = 128KB ; B stages 8 x 8KB = 64KB
#define SM_A(sl)  ((sl) * 16384)
#define SM_B(sl)  (131072 + (sl) * 8192)
#define GK_SMEM_BYTES 196608

// ---------------- the persistent kernel ----------------
__global__ __launch_bounds__(NTHR, 1) void recon_kernel(
    const float* __restrict__ dh, const int* __restrict__ caps,
    const float* __restrict__ W_attn, const float* __restrict__ U_attn,
    const float* __restrict__ b_attn, const float* __restrict__ w_attn,
    const float* __restrict__ W_ih, const float* __restrict__ W_hh,
    const float* __restrict__ b_ih, const float* __restrict__ b_hh,
    float* __restrict__ out, int T_feat)
{
    extern __shared__ __align__(1024) float smem[];
    __shared__ float bias_s[64];

    const int tid = threadIdx.x, blk = blockIdx.x;
    const int warp = tid >> 5, lane = tid & 31;
    int sense = 0;

    const int gm0 = (blk & 1) * 128;
    const int gn0 = (blk >> 1) * 16;

    char* smem_c = (char*)smem;
    const uint32_t smem_base = smem_u32(smem);

    if (tid < 64) {
        int row = (tid & 3) * 1024 + gn0 + (tid >> 2);
        bias_s[tid] = b_ih[row] + b_hh[row];
    }

    // ---- MMA mapping (shared by uv GEMM and gates): 2 groups x 8 warps ----
    const int grp = warp >> 3;
    const int wg  = warp & 7;
    const int wm  = (wg & 3) * 32;
    const int wn  = (wg >> 2) * 32;
    const int ls_row = ((lane >> 3) & 1) * 8 + (lane & 7);
    const int ls_colb = (lane >> 4) * 16;
    const uint32_t a_swz = SWZ((uint32_t)((wm + ls_row) * 128 + ls_colb));
    const uint32_t b_swz = SWZ((uint32_t)((wn + ls_row) * 128 + ls_colb));
    const int lr = lane >> 2, lc = lane & 3;

    // loader thread decomposition (A: 128 rows x 64 k per stage; B: 64 rows x 64 k)
    const int a_row = tid >> 2;
    const int a_c   = (tid & 3) * 16;
    const int a_so  = a_row * 128 + a_c * 2;
    const int b_row = tid >> 3;
    const int b_c   = (tid & 7) * 8;
    const int b_so  = b_row * 128 + b_c * 2;

    // ---- phase 0a: fp16 conversions + init ----
    for (int i = blk * NTHR + tid; i < BATCH * HID; i += NBLK * NTHR) {
        g_h_h[0][i] = __float2half_rn(0.0f);
        g_c[i]      = 0.0f;
    }
    for (int i = blk * NTHR + tid; i < 4 * HID * DEC; i += NBLK * NTHR)
        g_Wih_h[i] = __float2half_rn(W_ih[i]);
    for (int i = blk * NTHR + tid; i < 4 * HID * HID; i += NBLK * NTHR)
        g_Whh_h[i] = __float2half_rn(W_hh[i]);
    for (int i = blk * NTHR + tid; i < ATTN * HID; i += NBLK * NTHR) {
        g_Wa_h[i] = __float2half_rn(W_attn[i]);
        g_Ua_h[i] = __float2half_rn(U_attn[i]);
    }
    for (int i = blk * NTHR + tid; i < (T_CAP * BATCH * DEC) / 8; i += NBLK * NTHR) {
        float4 x = ((const float4*)dh)[2 * i];
        float4 y = ((const float4*)dh)[2 * i + 1];
        __half2 p0 = __floats2half2_rn(x.x, x.y);
        __half2 p1 = __floats2half2_rn(x.z, x.w);
        __half2 p2 = __floats2half2_rn(y.x, y.y);
        __half2 p3 = __floats2half2_rn(y.z, y.w);
        uint4 pk;
        pk.x = *(uint32_t*)&p0; pk.y = *(uint32_t*)&p1;
        pk.z = *(uint32_t*)&p2; pk.w = *(uint32_t*)&p3;
        ((uint4*)g_dh_h)[i] = pk;
    }

    // caption masks for this block's two batch rows (constant across steps)
    uint64_t mk[2];
    {
        const int b0 = blk * 2;
#pragma unroll
        for (int bi = 0; bi < 2; bi++) {
            uint64_t m = 0;
            for (int t = 0; t < T_CAP; t++) {
                int cp = __ldg(&caps[t * BATCH + b0 + bi]);
                if (cp != 0 && cp != 2) m |= (1ull << t);
            }
            mk[bi] = m;
        }
    }
    gsync(&sense);   // feats/Ua fp16 visible chip-wide

    // ---- phase 0b: Uv = feats @ U_attn^T + b_attn  (fp16 mma16, 2 tiles/block) ----
    for (int tix = blk; tix < 256; tix += NBLK) {
        const int m0 = (tix & 127) * 128;
        const int n0 = (tix >> 7) * 64;

        const int ar = m0 + a_row;                 // Uv row = b*64 + t
        const long a_gbase = ((long)((ar & 63) * 256 + (ar >> 6))) * 1024 + a_c;
        const long b_gbase = (long)(n0 + b_row) * 1024 + b_c;

        auto uv_load = [&](int p) {
            int sl = p & 7;
            int k0 = p * 64;
            const __half* Asrc = g_dh_h + a_gbase + k0;
            const __half* Bsrc = g_Ua_h + b_gbase + k0;
            char* Ab = smem_c + SM_A(sl);
            char* Bb = smem_c + SM_B(sl);
            cp16cg(Ab + SWZ(a_so),      Asrc);
            cp16cg(Ab + SWZ(a_so + 16), Asrc + 8);
            cp16(Bb + SWZ(b_so), Bsrc);
            CP_COMMIT();
        };

        float acc[2][4][4];
#pragma unroll
        for (int i = 0; i < 2; i++)
#pragma unroll
            for (int j = 0; j < 4; j++)
#pragma unroll
                for (int k = 0; k < 4; k++) acc[i][j][k] = 0.0f;

#pragma unroll
        for (int p = 0; p < 4; p++) uv_load(p);

        const int NP = 8;   // 16 stages (K=1024), pairs
        for (int t = 0; t < NP; t++) {
            int f = 2 * t + 4;
            if (f < 16)     uv_load(f);
            if (f + 1 < 16) uv_load(f + 1);
            if (t <= NP - 3)      { CP_WAIT(4); }
            else if (t == NP - 2) { CP_WAIT(2); }
            else                  { CP_WAIT(0); }
            __syncthreads();

            const int sl = (2 * t + grp) & 7;
            const uint32_t Ab = smem_base + SM_A(sl);
            const uint32_t Bb = smem_base + SM_B(sl);
#pragma unroll
            for (int kk = 0; kk < 4; kk++) {
                const uint32_t kofs = (uint32_t)(kk * 32);
                uint32_t af0[4], af1[4], bfa[4], bfb[4];
                ldsm4(af0, Ab + (a_swz ^ kofs));
                ldsm4(af1, Ab + 2048 + (a_swz ^ kofs));
                ldsm4(bfa, Bb + (b_swz ^ kofs));
                ldsm4(bfb, Bb + 2048 + (b_swz ^ kofs));
                uint32_t b0[2] = {bfa[0], bfa[2]};
                uint32_t b1[2] = {bfa[1], bfa[3]};
                uint32_t b2[2] = {bfb[0], bfb[2]};
                uint32_t b3[2] = {bfb[1], bfb[3]};
                mma16(acc[0][0], af0, b0);
                mma16(acc[0][1], af0, b1);
                mma16(acc[0][2], af0, b2);
                mma16(acc[0][3], af0, b3);
                mma16(acc[1][0], af1, b0);
                mma16(acc[1][1], af1, b1);
                mma16(acc[1][2], af1, b2);
                mma16(acc[1][3], af1, b3);
            }
        }

        __syncthreads();

        float (*gs0)[68] = (float(*)[68])smem;
        float (*gs1)[68] = (float(*)[68])(smem + 8704);
        {
            float (*gs)[68] = (grp == 0) ? gs0 : gs1;
#pragma unroll
            for (int fm = 0; fm < 2; fm++) {
#pragma unroll
                for (int fn = 0; fn < 4; fn++) {
                    int m = wm + fm * 16 + lr;
                    int j = wn + fn * 8 + 2 * lc;
                    *(float2*)&gs[m][j]     = make_float2(acc[fm][fn][0], acc[fm][fn][1]);
                    *(float2*)&gs[m + 8][j] = make_float2(acc[fm][fn][2], acc[fm][fn][3]);
                }
            }
        }
        __syncthreads();

        for (int q = tid; q < 128 * 16; q += NTHR) {
            int ml = q & 127, nl = q >> 7;
            float4 ga = *(float4*)&gs0[ml][nl * 4];
            float4 gb = *(float4*)&gs1[ml][nl * 4];
            int col = n0 + nl * 4;
            float v0 = ga.x + gb.x + b_attn[col + 0];
            float v1 = ga.y + gb.y + b_attn[col + 1];
            float v2 = ga.z + gb.z + b_attn[col + 2];
            float v3 = ga.w + gb.w + b_attn[col + 3];
            __half2 o0 = __floats2half2_rn(v0, v1);
            __half2 o1 = __floats2half2_rn(v2, v3);
            uint2 pk;
            pk.x = *(uint32_t*)&o0;
            pk.y = *(uint32_t*)&o1;
            *(uint2*)&g_Uv_h[(long)(m0 + ml) * ATTN + col] = pk;
        }
        __syncthreads();
    }
    gsync(&sense);

    // ---- gates loader global offsets ----
    const long a_goff = (long)(gm0 + a_row) * 1024 + a_c;
    const long b_goff = (long)((b_row & 3) * 1024 + gn0 + (b_row >> 2)) * 1024 + b_c;

    for (int s = 0; s < T_feat; s++) {
        const __half* hprev_h = g_h_h[s & 1];
        __half* hnext_h = g_h_h[(s + 1) & 1];

        // gates stage loader: processing order p=0..31 -> stage (p+16)&31 (h-half first),
        // slot (p+4)&7 (preload slots 4-7 avoid attention smem at 0-16KB).
        auto load_stage = [&](int p) {
            int st = (p + 16) & 31;
            int sl = (p + 4) & 7;
            int k0 = st * 64;
            int kb = k0 & 1023;
            const __half* Asrc = ((k0 < 1024) ? g_ctx_h : hprev_h) + a_goff + kb;
            const __half* Bsrc = ((k0 < 1024) ? g_Wih_h : g_Whh_h) + b_goff + kb;
            char* Ab = smem_c + SM_A(sl);
            char* Bb = smem_c + SM_B(sl);
            cp16cg(Ab + SWZ(a_so),      Asrc);
            cp16cg(Ab + SWZ(a_so + 16), Asrc + 8);
            cp16(Bb + SWZ(b_so), Bsrc);
            CP_COMMIT();
        };

        // ================= attention: 2 batch rows per block (fp16 inputs) =================
        {
            const int b0 = blk * 2;
            __half* hs_h = (__half*)smem;      // [2][1024] halves = 4 KB
            float* whs = smem + 1024;          // [2][128]
            float* wa  = smem + 1280;          // [128]
            float* es  = smem + 1536;          // [2][64]
            float* ps  = smem + 1664;          // [2][64]

            if (tid < 256)
                cp16cg(hs_h + tid * 8, (const __half*)hprev_h + b0 * HID + tid * 8);
            CP_COMMIT();
            if (tid < ATTN) wa[tid] = w_attn[tid];
            CP_WAIT(0);
            __syncthreads();

            // Wh: warp w owns 8 a-cols; fp16 W and h, fp32 accumulate
            const uint4* hs4 = (const uint4*)hs_h;
#pragma unroll
            for (int rr = 0; rr < 8; rr++) {
                int a = warp * 8 + rr;
                const uint4* wrow = (const uint4*)(g_Wa_h + a * 1024);
                float d0 = 0.f, d1 = 0.f;
#pragma unroll
                for (int j = 0; j < 4; j++) {
                    uint4 w4 = wrow[j * 32 + lane];
                    uint4 x4 = hs4[j * 32 + lane];
                    uint4 y4 = hs4[128 + j * 32 + lane];
                    const __half2* wh2 = (const __half2*)&w4;
                    const __half2* xh2 = (const __half2*)&x4;
                    const __half2* yh2 = (const __half2*)&y4;
#pragma unroll
                    for (int q = 0; q < 4; q++) {
                        float2 wf = __half22float2(wh2[q]);
                        float2 xf = __half22float2(xh2[q]);
                        float2 yf = __half22float2(yh2[q]);
                        d0 += wf.x * xf.x + wf.y * xf.y;
                        d1 += wf.x * yf.x + wf.y * yf.y;
                    }
                }
#pragma unroll
                for (int off = 16; off; off >>= 1) {
                    d0 += __shfl_xor_sync(0xffffffffu, d0, off);
                    d1 += __shfl_xor_sync(0xffffffffu, d1, off);
                }
                if (lane == 0) { whs[a] = d0; whs[128 + a] = d1; }
            }
            __syncthreads();

            // energies: fp16 Uv, mask from registers
            for (int t = warp; t < T_CAP; t += 16) {
#pragma unroll
                for (int bi = 0; bi < 2; bi++) {
                    const __half* uv = g_Uv_h + ((long)(b0 + bi) * T_CAP + t) * ATTN;
                    uint2 v = *(const uint2*)(uv + lane * 4);
                    float4 wv = *(float4*)&wa[lane * 4];
                    float4 hv = *(float4*)&whs[bi * 128 + lane * 4];
                    float2 f0 = __half22float2(*(__half2*)&v.x);
                    float2 f1 = __half22float2(*(__half2*)&v.y);
                    float sE = wv.x * tanh_fast(hv.x + f0.x)
                             + wv.y * tanh_fast(hv.y + f0.y)
                             + wv.z * tanh_fast(hv.z + f1.x)
                             + wv.w * tanh_fast(hv.w + f1.y);
#pragma unroll
                    for (int off = 16; off; off >>= 1)
                        sE += __shfl_xor_sync(0xffffffffu, sE, off);
                    if (lane == 0)
                        es[bi * 64 + t] = ((mk[bi] >> t) & 1) ? sE : -1e30f;
                }
            }
            __syncthreads();

            if (warp < 2) {
                int bi = warp;
                float e0 = es[bi * 64 + lane], e1 = es[bi * 64 + lane + 32];
                float mx = fmaxf(e0, e1);
#pragma unroll
                for (int off = 16; off; off >>= 1)
                    mx = fmaxf(mx, __shfl_xor_sync(0xffffffffu, mx, off));
                float x0 = __expf(e0 - mx), x1 = __expf(e1 - mx);
                float sm = x0 + x1;
#pragma unroll
                for (int off = 16; off; off >>= 1)
                    sm += __shfl_xor_sync(0xffffffffu, sm, off);
                float inv = 1.0f / sm;
                ps[bi * 64 + lane]      = x0 * inv;
                ps[bi * 64 + lane + 32] = x1 * inv;
            }
            __syncthreads();

            // ctx from fp16 feats, fp32 accumulate
            {
                const int row = tid >> 8;
                const int d4 = (tid & 255) * 4;
                float a0 = 0.f, a1 = 0.f, a2 = 0.f, a3 = 0.f;
                const float* pr = ps + row * 64;
#pragma unroll 4
                for (int t = 0; t < T_CAP; t++) {
                    float p = pr[t];
                    uint2 v = *(const uint2*)&g_dh_h[(long)(t * BATCH + b0 + row) * DEC + d4];
                    float2 f0 = __half22float2(*(__half2*)&v.x);
                    float2 f1 = __half22float2(*(__half2*)&v.y);
                    a0 += p * f0.x; a1 += p * f0.y; a2 += p * f1.x; a3 += p * f1.y;
                }
                __half2 o0 = __floats2half2_rn(a0, a1);
                __half2 o1 = __floats2half2_rn(a2, a3);
                uint2 pk;
                pk.x = *(uint32_t*)&o0;
                pk.y = *(uint32_t*)&o1;
                *(uint2*)&g_ctx_h[(long)(b0 + row) * DEC + d4] = pk;
            }
        }

        // preload first 4 gates stages (h-half: depends only on hprev + W_hh)
        load_stage(0);
        load_stage(1);
        load_stage(2);
        load_stage(3);

        gsync(&sense);

        // ===== gates: 128m x 64j x 2048k fp16; pair k-split, h-half first =====
        {
            const int NP = 16;   // stage pairs

            float acc[2][4][4];
#pragma unroll
            for (int i = 0; i < 2; i++)
#pragma unroll
                for (int j = 0; j < 4; j++)
#pragma unroll
                    for (int k = 0; k < 4; k++) acc[i][j][k] = 0.0f;

            for (int t = 0; t < NP; t++) {
                int f = 2 * t + 4;
                if (f < 32)     load_stage(f);
                if (f + 1 < 32) load_stage(f + 1);
                if (t <= NP - 3)      { CP_WAIT(4); }
                else if (t == NP - 2) { CP_WAIT(2); }
                else                  { CP_WAIT(0); }
                __syncthreads();

                const int sl = (2 * t + grp + 4) & 7;
                const uint32_t Ab = smem_base + SM_A(sl);
                const uint32_t Bb = smem_base + SM_B(sl);
#pragma unroll
                for (int kk = 0; kk < 4; kk++) {
                    const uint32_t kofs = (uint32_t)(kk * 32);
                    uint32_t af0[4], af1[4], bfa[4], bfb[4];
                    ldsm4(af0, Ab + (a_swz ^ kofs));
                    ldsm4(af1, Ab + 2048 + (a_swz ^ kofs));
                    ldsm4(bfa, Bb + (b_swz ^ kofs));
                    ldsm4(bfb, Bb + 2048 + (b_swz ^ kofs));
                    uint32_t b0[2] = {bfa[0], bfa[2]};
                    uint32_t b1[2] = {bfa[1], bfa[3]};
                    uint32_t b2[2] = {bfb[0], bfb[2]};
                    uint32_t b3[2] = {bfb[1], bfb[3]};
                    mma16(acc[0][0], af0, b0);
                    mma16(acc[0][1], af0, b1);
                    mma16(acc[0][2], af0, b2);
                    mma16(acc[0][3], af0, b3);
                    mma16(acc[1][0], af1, b0);
                    mma16(acc[1][1], af1, b1);
                    mma16(acc[1][2], af1, b2);
                    mma16(acc[1][3], af1, b3);
                }
            }

            __syncthreads();  // stage smem dead; overlay two gates tiles

            float (*gs0)[68] = (float(*)[68])smem;            // grp 0
            float (*gs1)[68] = (float(*)[68])(smem + 8704);   // grp 1
            {
                float (*gs)[68] = (grp == 0) ? gs0 : gs1;
#pragma unroll
                for (int fm = 0; fm < 2; fm++) {
#pragma unroll
                    for (int fn = 0; fn < 4; fn++) {
                        int m = wm + fm * 16 + lr;
                        int j = wn + fn * 8 + 2 * lc;
                        *(float2*)&gs[m][j]     = make_float2(acc[fm][fn][0], acc[fm][fn][1]);
                        *(float2*)&gs[m + 8][j] = make_float2(acc[fm][fn][2], acc[fm][fn][3]);
                    }
                }
            }
            __syncthreads();

            for (int q = tid; q < 128 * 16; q += NTHR) {
                int ml = q & 127, nl = q >> 7;
                float4 ga = *(float4*)&gs0[ml][nl * 4];
                float4 gb = *(float4*)&gs1[ml][nl * 4];
                float iv = ga.x + gb.x + bias_s[nl * 4 + 0];
                float fv = ga.y + gb.y + bias_s[nl * 4 + 1];
                float gv = ga.z + gb.z + bias_s[nl * 4 + 2];
                float ov = ga.w + gb.w + bias_s[nl * 4 + 3];
                int b = gm0 + ml, n = gn0 + nl;
                int idx = b * HID + n;
                float cold = g_c[idx];
                float cn = sigf(fv) * cold + sigf(iv) * tanhf(gv);
                float hn = sigf(ov) * tanhf(cn);
                g_c[idx] = cn;
                hnext_h[idx] = __float2half_rn(hn);
                out[(long)(b * T_feat + s) * HID + n] = hn;
            }
        }
        gsync(&sense);
    }
    // total gsyncs: 2 + 2*T_feat = 58 (even) -> g_flag restored to 0 for graph replay
}

// ---------------- launcher ----------------
extern "C" void kernel_launch(void* const* d_in, const int* in_sizes, int n_in,
                              void* d_out, int out_size)
{
    int base = 2;
    if (n_in >= 11 && in_sizes[2] == 1) base = 3;

    const float* dh     = (const float*)d_in[0];
    const int*   caps   = (const int*)d_in[1];
    const float* W_attn = (const float*)d_in[base + 0];
    const float* U_attn = (const float*)d_in[base + 1];
    const float* b_attn = (const float*)d_in[base + 2];
    const float* w_attn = (const float*)d_in[base + 3];
    const float* W_ih   = (const float*)d_in[base + 4];
    const float* W_hh   = (const float*)d_in[base + 5];
    const float* b_ih   = (const float*)d_in[base + 6];
    const float* b_hh   = (const float*)d_in[base + 7];
    float* out = (float*)d_out;

    const int T_feat = out_size / (BATCH * HID);  // 28

    static int configured = 0;
    if (!configured) {
        cudaFuncSetAttribute(recon_kernel, cudaFuncAttributeMaxDynamicSharedMemorySize,
                             GK_SMEM_BYTES);
        configured = 1;
    }

    recon_kernel<<<NBLK, NTHR, GK_SMEM_BYTES>>>(
        dh, caps, W_attn, U_attn, b_attn, w_attn,
        W_ih, W_hh, b_ih, b_hh, out, T_feat);
}